// round 1
// baseline (speedup 1.0000x reference)
#include <cuda_runtime.h>
#include <cstdint>

// Problem constants (shapes are fixed by the dataset)
#define C_NV 100000
#define C_NC 400000
#define C_NU 64
#define C_E  1200000
#define C_D  128

// ---------------- scratch (device globals; no allocation allowed) ----------
__device__ float g_hc[(size_t)C_NC * C_D];     // clause message accumulators
__device__ float g_hv[(size_t)C_NV * C_D];     // var message accumulators
__device__ float g_cnt_c[C_NC];
__device__ float g_cnt_v[C_NV];
__device__ float g_Pv[(size_t)C_NV * C_D];     // var_emb @ W_vc[4:132]
__device__ float g_Pc[(size_t)C_NC * C_D];     // clause_emb @ W_cv[4:132]
__device__ float g_Qc[C_NU * C_D];             // ctx_emb @ W_c[144:272]
__device__ float g_Qv[C_NU * C_D];             // ctx_emb @ W_v[144:272]
__device__ float g_ctx_acc[2 * C_NU * C_D];    // [clause sums | var sums]
__device__ float g_ctx_cnt[2 * C_NU];

static __device__ __forceinline__ float lrelu(float x) {
    return x >= 0.f ? x : 0.1f * x;
}

// ---------------- zero ------------------------------------------------------
__global__ void zero_kernel(float4* __restrict__ p, long n4) {
    long i = (long)blockIdx.x * blockDim.x + threadIdx.x;
    long stride = (long)gridDim.x * blockDim.x;
    float4 z = make_float4(0.f, 0.f, 0.f, 0.f);
    for (; i < n4; i += stride) p[i] = z;
}

// ---------------- fused multi-segment GEMM ---------------------------------
// out[row, :] = act( Af[row]@Wf + (Ah[row]/max(cnt,1))@Wh + Ae[row]@We
//                    + bias + Q[qidx[row]] )
// N = 128 fixed. Tile: BM=64, BK=16, 256 threads, each thread 8x4 outputs.
__global__ __launch_bounds__(256, 2) void fused_gemm(
    int M,
    const float* __restrict__ Af, int KF, const float* __restrict__ Wf,
    const float* __restrict__ Ah, const float* __restrict__ cntp,
    const float* __restrict__ Wh,
    const float* __restrict__ Ae, const float* __restrict__ We,
    const float* __restrict__ bias,
    const float* __restrict__ Q, const int* __restrict__ qidx,
    int act, float* __restrict__ out)
{
    __shared__ float As[64][16];
    __shared__ float Ws[16][128];

    const int t  = threadIdx.x;
    const int tx = t & 31;          // column group: cols tx*4 .. tx*4+3
    const int ty = t >> 5;          // row group: rows ty*8 .. ty*8+7
    const int row0 = blockIdx.x * 64;

    float acc[8][4];
#pragma unroll
    for (int r = 0; r < 8; r++) {
        acc[r][0] = acc[r][1] = acc[r][2] = acc[r][3] = 0.f;
    }

    const int aRow = t >> 2;        // 0..63
    const int aK   = (t & 3) * 4;   // 0,4,8,12
    const int wK   = t >> 4;        // 0..15
    const int wC   = (t & 15) * 8;  // 0..120

    int arow_g = row0 + aRow;
    if (arow_g >= M) arow_g = M - 1;   // clamp for loads; stores are guarded

    const float* Aseg[3] = { Af, Ah, Ae };
    const float* Wseg[3] = { Wf, Wh, We };
    const int    Kseg[3] = { KF, 128, 128 };

    for (int s = 0; s < 3; s++) {
        const float* A = Aseg[s];
        if (!A) continue;
        const float* W = Wseg[s];
        const int K = Kseg[s];
        float scale = 1.f;
        if (s == 1) scale = 1.f / fmaxf(cntp[arow_g], 1.f);

        for (int kk = 0; kk < K; kk += 16) {
            __syncthreads();
            // A tile: each thread one float4
            float4 av = *(const float4*)(A + (size_t)arow_g * K + kk + aK);
            av.x *= scale; av.y *= scale; av.z *= scale; av.w *= scale;
            *(float4*)&As[aRow][aK] = av;
            // W tile: each thread 8 floats (two float4)
            const float* wp = W + (size_t)(kk + wK) * 128 + wC;
            *(float4*)&Ws[wK][wC]     = *(const float4*)(wp);
            *(float4*)&Ws[wK][wC + 4] = *(const float4*)(wp + 4);
            __syncthreads();

#pragma unroll
            for (int k = 0; k < 16; k++) {
                float4 w = *(const float4*)&Ws[k][tx * 4];
#pragma unroll
                for (int r = 0; r < 8; r++) {
                    float a = As[ty * 8 + r][k];
                    acc[r][0] = fmaf(a, w.x, acc[r][0]);
                    acc[r][1] = fmaf(a, w.y, acc[r][1]);
                    acc[r][2] = fmaf(a, w.z, acc[r][2]);
                    acc[r][3] = fmaf(a, w.w, acc[r][3]);
                }
            }
        }
    }

    // epilogue
    float4 bv = make_float4(0.f, 0.f, 0.f, 0.f);
    if (bias) bv = *(const float4*)(bias + tx * 4);

#pragma unroll
    for (int r = 0; r < 8; r++) {
        int row = row0 + ty * 8 + r;
        if (row < M) {
            float4 v;
            v.x = acc[r][0] + bv.x;
            v.y = acc[r][1] + bv.y;
            v.z = acc[r][2] + bv.z;
            v.w = acc[r][3] + bv.w;
            if (Q) {
                int qi = qidx[row];
                float4 q = *(const float4*)(Q + (size_t)qi * 128 + tx * 4);
                v.x += q.x; v.y += q.y; v.z += q.z; v.w += q.w;
            }
            if (act) {
                v.x = lrelu(v.x); v.y = lrelu(v.y);
                v.z = lrelu(v.z); v.w = lrelu(v.w);
            }
            *(float4*)(out + (size_t)row * 128 + tx * 4) = v;
        }
    }
}

// ---------------- edge message + scatter ------------------------------------
// per edge e: m = lrelu(b + edge_sat[e] @ W1 + P[src[e]]);
//             acc[dst[e]] += m (vector red); cnt[dst[e]] += 1
__global__ __launch_bounds__(256) void edge_kernel(
    int E,
    const float* __restrict__ es,    // E x 4
    const int*   __restrict__ src,
    const int*   __restrict__ dst,
    const float* __restrict__ P,     // Nsrc x 128
    const float* __restrict__ W1,    // 4 x 128 (rows 0..3 of W)
    const float* __restrict__ b,     // 128
    float* __restrict__ acc,
    float* __restrict__ cnt)
{
    const int lane = threadIdx.x & 31;
    const int c = lane * 4;

    // loop-invariant weight/bias slice for this lane's 4 columns
    float w[4][4], bb[4];
#pragma unroll
    for (int r = 0; r < 4; r++)
#pragma unroll
        for (int i = 0; i < 4; i++)
            w[r][i] = W1[r * 128 + c + i];
#pragma unroll
    for (int i = 0; i < 4; i++) bb[i] = b[c + i];

    int warp  = blockIdx.x * (blockDim.x >> 5) + (threadIdx.x >> 5);
    int nwarp = gridDim.x * (blockDim.x >> 5);

    for (int e = warp; e < E; e += nwarp) {
        int s = src[e], d = dst[e];
        float4 ev = *(const float4*)(es + (size_t)e * 4);
        float4 p  = *(const float4*)(P + (size_t)s * 128 + c);
        float m0 = bb[0], m1 = bb[1], m2 = bb[2], m3 = bb[3];
        m0 = fmaf(ev.x, w[0][0], m0); m0 = fmaf(ev.y, w[1][0], m0);
        m0 = fmaf(ev.z, w[2][0], m0); m0 = fmaf(ev.w, w[3][0], m0);
        m1 = fmaf(ev.x, w[0][1], m1); m1 = fmaf(ev.y, w[1][1], m1);
        m1 = fmaf(ev.z, w[2][1], m1); m1 = fmaf(ev.w, w[3][1], m1);
        m2 = fmaf(ev.x, w[0][2], m2); m2 = fmaf(ev.y, w[1][2], m2);
        m2 = fmaf(ev.z, w[2][2], m2); m2 = fmaf(ev.w, w[3][2], m2);
        m3 = fmaf(ev.x, w[0][3], m3); m3 = fmaf(ev.y, w[1][3], m3);
        m3 = fmaf(ev.z, w[2][3], m3); m3 = fmaf(ev.w, w[3][3], m3);
        m0 = lrelu(m0 + p.x);
        m1 = lrelu(m1 + p.y);
        m2 = lrelu(m2 + p.z);
        m3 = lrelu(m3 + p.w);

        float* ap = acc + (size_t)d * 128 + c;
#if __CUDA_ARCH__ >= 900
        asm volatile("red.global.add.v4.f32 [%0], {%1, %2, %3, %4};"
                     :: "l"(ap), "f"(m0), "f"(m1), "f"(m2), "f"(m3)
                     : "memory");
#else
        atomicAdd(ap + 0, m0); atomicAdd(ap + 1, m1);
        atomicAdd(ap + 2, m2); atomicAdd(ap + 3, m3);
#endif
        if (lane == 0) atomicAdd(cnt + d, 1.f);
    }
}

// ---------------- segment mean into NU=64 contexts --------------------------
__global__ __launch_bounds__(128) void seg_mean_ctx(
    const float* __restrict__ srcm, const int* __restrict__ ids, int n,
    float* __restrict__ acc, float* __restrict__ cntp)
{
    __shared__ float sacc[64 * 128];
    __shared__ float scnt[64];
    const int t = threadIdx.x;
    for (int i = t; i < 64 * 128; i += 128) sacc[i] = 0.f;
    if (t < 64) scnt[t] = 0.f;
    __syncthreads();

    for (long r0 = (long)blockIdx.x * 4; r0 < n; r0 += (long)gridDim.x * 4) {
        float v[4]; int id[4]; int k = 0;
#pragma unroll
        for (int u = 0; u < 4; u++) {
            long r = r0 + u;
            if (r < n) {
                id[k] = ids[r];
                v[k]  = srcm[(size_t)r * 128 + t];
                k++;
            }
        }
        for (int u = 0; u < k; u++) {
            sacc[id[u] * 128 + t] += v[u];
            if (t == 0) scnt[id[u]] += 1.f;
        }
    }
    __syncthreads();
    for (int i = t; i < 64 * 128; i += 128) atomicAdd(&acc[i], sacc[i]);
    if (t < 64) atomicAdd(&cntp[t], scnt[t]);
}

// ---------------- context update (64 rows, K=400) ---------------------------
__global__ __launch_bounds__(128) void ctx_update(
    const float* __restrict__ ctx_feats,   // 64 x 16
    const float* __restrict__ ctx_emb,     // 64 x 128
    const float* __restrict__ acc,         // [64*128 clause | 64*128 var]
    const float* __restrict__ cntp,        // [64 clause | 64 var]
    const float* __restrict__ Wu,          // 400 x 128
    const float* __restrict__ bu,          // 128
    float* __restrict__ out)               // 64 x 128
{
    const int u = blockIdx.x;
    const int t = threadIdx.x;
    __shared__ float a[400];

    if (t < 16) a[t] = ctx_feats[u * 16 + t];
    float cc = fmaxf(cntp[u], 1.f);
    float cv = fmaxf(cntp[64 + u], 1.f);
    a[16 + t]  = acc[u * 128 + t] / cc;
    a[144 + t] = acc[64 * 128 + u * 128 + t] / cv;
    a[272 + t] = ctx_emb[u * 128 + t];
    __syncthreads();

    float s = bu[t];
    for (int k = 0; k < 400; k++) s = fmaf(a[k], Wu[k * 128 + t], s);
    out[(size_t)u * 128 + t] = lrelu(s);
}

// ---------------- launch ----------------------------------------------------
extern "C" void kernel_launch(void* const* d_in, const int* in_sizes, int n_in,
                              void* d_out, int out_size)
{
    const float* var_emb      = (const float*)d_in[0];
    const float* clause_emb   = (const float*)d_in[1];
    const float* ctx_emb      = (const float*)d_in[2];
    const float* var_feats    = (const float*)d_in[3];
    const float* clause_feats = (const float*)d_in[4];
    const float* ctx_feats    = (const float*)d_in[5];
    const float* edge_sat_vc  = (const float*)d_in[6];
    const float* edge_sat_cv  = (const float*)d_in[7];
    const float* W_vc         = (const float*)d_in[8];
    const float* b_vc         = (const float*)d_in[9];
    const float* W_cv         = (const float*)d_in[10];
    const float* b_cv         = (const float*)d_in[11];
    const float* W_c          = (const float*)d_in[12];
    const float* b_c          = (const float*)d_in[13];
    const float* W_v          = (const float*)d_in[14];
    const float* b_v          = (const float*)d_in[15];
    const float* W_u          = (const float*)d_in[16];
    const float* b_u          = (const float*)d_in[17];
    const int* assigns_src    = (const int*)d_in[18];
    const int* assigns_dst    = (const int*)d_in[19];
    const int* contains_src   = (const int*)d_in[20];
    const int* contains_dst   = (const int*)d_in[21];
    const int* var_ctx        = (const int*)d_in[22];
    const int* clause_ctx     = (const int*)d_in[23];

    const int NV = in_sizes[0] / C_D;
    const int NC = in_sizes[1] / C_D;
    const int E  = in_sizes[18];

    float *hc, *hv, *cc, *cv, *Pv, *Pc, *Qc, *Qv, *cacc, *ccnt;
    cudaGetSymbolAddress((void**)&hc,   g_hc);
    cudaGetSymbolAddress((void**)&hv,   g_hv);
    cudaGetSymbolAddress((void**)&cc,   g_cnt_c);
    cudaGetSymbolAddress((void**)&cv,   g_cnt_v);
    cudaGetSymbolAddress((void**)&Pv,   g_Pv);
    cudaGetSymbolAddress((void**)&Pc,   g_Pc);
    cudaGetSymbolAddress((void**)&Qc,   g_Qc);
    cudaGetSymbolAddress((void**)&Qv,   g_Qv);
    cudaGetSymbolAddress((void**)&cacc, g_ctx_acc);
    cudaGetSymbolAddress((void**)&ccnt, g_ctx_cnt);

    float* out = (float*)d_out;

    auto zero = [](float* p, long n) {
        long n4 = n / 4;
        int blocks = (int)((n4 + 255) / 256);
        if (blocks > 4096) blocks = 4096;
        zero_kernel<<<blocks, 256>>>((float4*)p, n4);
    };

    // zero accumulators
    zero(hc, (long)NC * C_D);
    zero(hv, (long)NV * C_D);
    zero(cc, NC);
    zero(cv, NV);
    zero(cacc, 2 * C_NU * C_D);
    zero(ccnt, 2 * C_NU);

    // Precompute projections (gather/GEMM commutation)
    // P_v = var_emb @ W_vc[4:132], P_c = clause_emb @ W_cv[4:132]
    fused_gemm<<<(NV + 63) / 64, 256>>>(NV,
        nullptr, 0, nullptr, nullptr, nullptr, nullptr,
        var_emb, W_vc + 4 * C_D,
        nullptr, nullptr, nullptr, 0, Pv);
    fused_gemm<<<(NC + 63) / 64, 256>>>(NC,
        nullptr, 0, nullptr, nullptr, nullptr, nullptr,
        clause_emb, W_cv + 4 * C_D,
        nullptr, nullptr, nullptr, 0, Pc);
    // Q_c = ctx_emb @ W_c[144:272], Q_v = ctx_emb @ W_v[144:272]
    fused_gemm<<<1, 256>>>(C_NU,
        nullptr, 0, nullptr, nullptr, nullptr, nullptr,
        ctx_emb, W_c + 144 * C_D,
        nullptr, nullptr, nullptr, 0, Qc);
    fused_gemm<<<1, 256>>>(C_NU,
        nullptr, 0, nullptr, nullptr, nullptr, nullptr,
        ctx_emb, W_v + 144 * C_D,
        nullptr, nullptr, nullptr, 0, Qv);

    // Edge messages + segment-sum scatter
    edge_kernel<<<4096, 256>>>(E, edge_sat_vc, assigns_src, assigns_dst,
                               Pv, W_vc, b_vc, hc, cc);
    edge_kernel<<<4096, 256>>>(E, edge_sat_cv, contains_src, contains_dst,
                               Pc, W_cv, b_cv, hv, cv);

    // Node updates (write directly into d_out)
    // new_clause rows [0, NC)
    fused_gemm<<<(NC + 63) / 64, 256>>>(NC,
        clause_feats, 16, W_c,
        hc, cc, W_c + 16 * C_D,
        clause_emb, W_c + 272 * C_D,
        b_c, Qc, clause_ctx, 1, out);
    // new_var rows [NC, NC+NV)
    fused_gemm<<<(NV + 63) / 64, 256>>>(NV,
        var_feats, 16, W_v,
        hv, cv, W_v + 16 * C_D,
        var_emb, W_v + 272 * C_D,
        b_v, Qv, var_ctx, 1, out + (size_t)NC * C_D);

    // Context means over the NEW embeddings
    seg_mean_ctx<<<1024, 128>>>(out, clause_ctx, NC, cacc, ccnt);
    seg_mean_ctx<<<1024, 128>>>(out + (size_t)NC * C_D, var_ctx, NV,
                                cacc + C_NU * C_D, ccnt + C_NU);

    // Context update: rows [NC+NV, NC+NV+NU)
    ctx_update<<<C_NU, 128>>>(ctx_feats, ctx_emb, cacc, ccnt, W_u, b_u,
                              out + (size_t)(NC + NV) * C_D);
}

// round 3
// speedup vs baseline: 1.1153x; 1.1153x over previous
#include <cuda_runtime.h>
#include <cuda_bf16.h>
#include <cstdint>

// Problem constants (fixed by the dataset)
#define C_NV 100000
#define C_NC 400000
#define C_NU 64
#define C_E  1200000
#define C_D  128

// ---------------- scratch (device globals; no allocation allowed) ----------
__device__ float g_hc[(size_t)C_NC * C_D];     // clause message accumulators
__device__ float g_hv[(size_t)C_NV * C_D];     // var message accumulators
__device__ float g_cnt_c[C_NC];
__device__ float g_cnt_v[C_NV];
__device__ float g_Pv[(size_t)C_NV * C_D];     // var_emb @ W_vc[4:132]
__device__ float g_Pc[(size_t)C_NC * C_D];     // clause_emb @ W_cv[4:132]
__device__ float g_Qc[C_NU * C_D];             // ctx_emb @ W_c[144:272]
__device__ float g_Qv[C_NU * C_D];             // ctx_emb @ W_v[144:272]
__device__ float g_ctx_acc[2 * C_NU * C_D];    // [clause sums | var sums]
__device__ float g_ctx_cnt[2 * C_NU];

// Transposed + bf16-split weight buffers: layout [n (0..127)][k (0..K-1)]
__device__ __align__(16) __nv_bfloat16 g_Bvc_h[128 * 128];
__device__ __align__(16) __nv_bfloat16 g_Bvc_l[128 * 128];
__device__ __align__(16) __nv_bfloat16 g_Bcv_h[128 * 128];
__device__ __align__(16) __nv_bfloat16 g_Bcv_l[128 * 128];
__device__ __align__(16) __nv_bfloat16 g_Bc_h[128 * 272];
__device__ __align__(16) __nv_bfloat16 g_Bc_l[128 * 272];
__device__ __align__(16) __nv_bfloat16 g_Bv_h[128 * 272];
__device__ __align__(16) __nv_bfloat16 g_Bv_l[128 * 272];

static __device__ __forceinline__ float lrelu(float x) {
    return x >= 0.f ? x : 0.1f * x;
}

static __device__ __forceinline__ uint32_t smem_u32(const void* p) {
    uint32_t a;
    asm("{ .reg .u64 t; cvta.to.shared.u64 t, %1; cvt.u32.u64 %0, t; }"
        : "=r"(a) : "l"(p));
    return a;
}

// ldmatrix x4 (non-transposed)
#define LDM4(d, addr)                                                          \
    asm volatile(                                                              \
        "ldmatrix.sync.aligned.m8n8.x4.shared.b16 {%0,%1,%2,%3}, [%4];"        \
        : "=r"((d)[0]), "=r"((d)[1]), "=r"((d)[2]), "=r"((d)[3])               \
        : "r"(addr))

// mma.sync m16n8k16 bf16 -> fp32
#define MMA16816(c, a, b0, b1)                                                 \
    asm volatile(                                                              \
        "mma.sync.aligned.m16n8k16.row.col.f32.bf16.bf16.f32 "                 \
        "{%0,%1,%2,%3}, {%4,%5,%6,%7}, {%8,%9}, {%0,%1,%2,%3};"                \
        : "+f"((c)[0]), "+f"((c)[1]), "+f"((c)[2]), "+f"((c)[3])               \
        : "r"((a)[0]), "r"((a)[1]), "r"((a)[2]), "r"((a)[3]),                  \
          "r"(b0), "r"(b1))

// fp32 -> packed (bf16 hi pair, bf16 lo pair)
static __device__ __forceinline__ void split2(
    float a, float b, uint32_t& hi, uint32_t& lo)
{
    __nv_bfloat16 ah = __float2bfloat16(a);
    __nv_bfloat16 bh = __float2bfloat16(b);
    float ar = a - __bfloat162float(ah);
    float br = b - __bfloat162float(bh);
    __nv_bfloat16 al = __float2bfloat16(ar);
    __nv_bfloat16 bl = __float2bfloat16(br);
    hi = (uint32_t)__bfloat16_as_ushort(ah) |
         ((uint32_t)__bfloat16_as_ushort(bh) << 16);
    lo = (uint32_t)__bfloat16_as_ushort(al) |
         ((uint32_t)__bfloat16_as_ushort(bl) << 16);
}

// ---------------- zero all accumulators (single launch) --------------------
__global__ void zero_all(float4* hc, long n0, float4* hv, long n1,
                         float4* cc, long n2, float4* cv, long n3,
                         float4* cacc, long n4, float4* ccnt, long n5)
{
    long i = (long)blockIdx.x * blockDim.x + threadIdx.x;
    long stride = (long)gridDim.x * blockDim.x;
    float4 z = make_float4(0.f, 0.f, 0.f, 0.f);
    long t01 = n0 + n1, t02 = t01 + n2, t03 = t02 + n3, t04 = t03 + n4;
    long tot = t04 + n5;
    for (; i < tot; i += stride) {
        if (i < n0)       hc[i] = z;
        else if (i < t01) hv[i - n0] = z;
        else if (i < t02) cc[i - t01] = z;
        else if (i < t03) cv[i - t02] = z;
        else if (i < t04) cacc[i - t03] = z;
        else              ccnt[i - t04] = z;
    }
}

// ---------------- weight transpose + bf16 hi/lo split -----------------------
__global__ void wprep(const float* __restrict__ Wvc, const float* __restrict__ Wcv,
                      const float* __restrict__ Wc,  const float* __restrict__ Wv)
{
    int i = blockIdx.x * blockDim.x + threadIdx.x;
    if (i >= 102400) return;
    float w;
    __nv_bfloat16 *dh, *dl;
    int di;
    if (i < 16384) {                       // vc: K=128, W rows 4..131
        int n = i >> 7, k = i & 127;
        w = Wvc[(4 + k) * 128 + n];
        dh = g_Bvc_h; dl = g_Bvc_l; di = n * 128 + k;
    } else if (i < 32768) {                // cv: K=128, W rows 4..131
        int j = i - 16384;
        int n = j >> 7, k = j & 127;
        w = Wcv[(4 + k) * 128 + n];
        dh = g_Bcv_h; dl = g_Bcv_l; di = n * 128 + k;
    } else if (i < 67584) {                // c: K=272, W rows {0..143, 272..399}
        int j = i - 32768;
        int n = j / 272, k = j % 272;
        int kk = (k < 144) ? k : k + 128;
        w = Wc[kk * 128 + n];
        dh = g_Bc_h; dl = g_Bc_l; di = n * 272 + k;
    } else {                               // v: K=272
        int j = i - 67584;
        int n = j / 272, k = j % 272;
        int kk = (k < 144) ? k : k + 128;
        w = Wv[kk * 128 + n];
        dh = g_Bv_h; dl = g_Bv_l; di = n * 272 + k;
    }
    __nv_bfloat16 h = __float2bfloat16(w);
    float r = w - __bfloat162float(h);
    dh[di] = h;
    dl[di] = __float2bfloat16(r);
}

// ---------------- HMMA GEMM (bf16x3 error-compensated) ----------------------
// out[row,:] = act( [Af | Ah/max(cnt,1) | Ae] @ B^T + bias + Q[qidx[row]] )
// B (hi/lo) is [128 n][Ktot k] bf16 in gmem; fully resident in smem.
// Tile M=128, N=128, BK=32 chunks; double-buffered A staging w/ reg prefetch.
// smem: Bs_hi [128][280], Bs_lo [128][280], As[2 buf][hi/lo][128][40]
#define B_STRIDE 280
#define A_STRIDE 40
#define SMEM_B_BYTES (128 * B_STRIDE * 2)         // 71680 per half
#define SMEM_A_BYTES (128 * A_STRIDE * 2)         // 10240 per half
#define SMEM_TOTAL_TC (2 * SMEM_B_BYTES + 4 * SMEM_A_BYTES)  // 184320

__global__ __launch_bounds__(256, 1) void tc_gemm(
    int M,
    const float* __restrict__ Af, int KF,
    const float* __restrict__ Ah, const float* __restrict__ cnt,
    const float* __restrict__ Ae,
    const __nv_bfloat16* __restrict__ Bh, const __nv_bfloat16* __restrict__ Bl,
    int Ktot,
    const float* __restrict__ bias, const float* __restrict__ Q,
    const int* __restrict__ qidx, int act,
    float* __restrict__ out)
{
    extern __shared__ char smem[];
    const uint32_t sb = smem_u32(smem);
    const uint32_t bs_hi = sb;
    const uint32_t bs_lo = sb + SMEM_B_BYTES;
    const uint32_t as0   = sb + 2 * SMEM_B_BYTES;

    const int tid  = threadIdx.x;
    const int wid  = tid >> 5;
    const int lane = tid & 31;

    // ---- load full B (hi+lo) into smem ----
    {
        const int kq = Ktot >> 3;          // uint4 (8 bf16) groups per row
        const int total = 128 * kq;
        for (int i = tid; i < total; i += 256) {
            int row = i / kq, kb = (i - row * kq) * 8;
            uint4 vh = *(const uint4*)(Bh + (size_t)row * Ktot + kb);
            uint4 vl = *(const uint4*)(Bl + (size_t)row * Ktot + kb);
            *(uint4*)(smem + (size_t)(row * B_STRIDE + kb) * 2) = vh;
            *(uint4*)(smem + SMEM_B_BYTES + (size_t)(row * B_STRIDE + kb) * 2) = vl;
        }
    }

    // ---- per-thread A staging assignment ----
    const int row0 = blockIdx.x * 128;
    const int r = tid >> 1;            // staged row 0..127
    const int h = tid & 1;             // col half: h*16 .. h*16+15
    int grow = row0 + r;
    if (grow >= M) grow = M - 1;       // clamp loads; stores guarded
    float inv = 1.f;
    if (cnt) inv = 1.f / fmaxf(cnt[grow], 1.f);

    const int nchunks = (Ktot + 31) >> 5;

    // accumulators: warp tile 64(m) x 32(n); 4 m16-tiles x 4 n8-tiles
    const int m_base = (wid & 1) * 64;
    const int n_base = (wid >> 1) * 32;
    float acc[4][4][4];
#pragma unroll
    for (int mt = 0; mt < 4; mt++)
#pragma unroll
        for (int nt = 0; nt < 4; nt++)
            acc[mt][nt][0] = acc[mt][nt][1] = acc[mt][nt][2] = acc[mt][nt][3] = 0.f;

    // ldmatrix per-lane patterns
    const int lmA_row = lane & 15;
    const int lmA_ko  = (lane >> 4) * 8;
    const int lmB_n   = (lane & 7) + ((lane >> 4) & 1) * 8;
    const int lmB_ko  = ((lane >> 3) & 1) * 8;

    // ---- prefetch chunk 0 ----
    float4 va[4];
    {
        const int k0 = 0;
#pragma unroll
        for (int j = 0; j < 4; j++) {
            int gk = k0 + h * 16 + j * 4;
            float4 v = make_float4(0.f, 0.f, 0.f, 0.f);
            if (gk < KF) v = *(const float4*)(Af + (size_t)grow * KF + gk);
            else if (gk < KF + 128) {
                v = *(const float4*)(Ah + (size_t)grow * 128 + (gk - KF));
                v.x *= inv; v.y *= inv; v.z *= inv; v.w *= inv;
            } else if (gk < Ktot) {
                v = *(const float4*)(Ae + (size_t)grow * 128 + (gk - KF - 128));
            }
            va[j] = v;
        }
    }

    for (int c = 0; c < nchunks; c++) {
        const int b = c & 1;
        const uint32_t a_hi = as0 + b * (2 * SMEM_A_BYTES);
        const uint32_t a_lo = a_hi + SMEM_A_BYTES;

        // ---- convert + store staged A chunk ----
#pragma unroll
        for (int j = 0; j < 4; j++) {
            int col = h * 16 + j * 4;
            uint2 hiv, lov;
            split2(va[j].x, va[j].y, hiv.x, lov.x);
            split2(va[j].z, va[j].w, hiv.y, lov.y);
            uint32_t off = (uint32_t)(r * A_STRIDE + col) * 2;
            *(uint2*)(smem + (a_hi - sb) + off) = hiv;
            *(uint2*)(smem + (a_lo - sb) + off) = lov;
        }
        __syncthreads();

        // ---- prefetch next chunk (LDGs overlap MMA below) ----
        if (c + 1 < nchunks) {
            const int k0 = (c + 1) * 32;
#pragma unroll
            for (int j = 0; j < 4; j++) {
                int gk = k0 + h * 16 + j * 4;
                float4 v = make_float4(0.f, 0.f, 0.f, 0.f);
                if (gk < KF) v = *(const float4*)(Af + (size_t)grow * KF + gk);
                else if (gk < KF + 128) {
                    v = *(const float4*)(Ah + (size_t)grow * 128 + (gk - KF));
                    v.x *= inv; v.y *= inv; v.z *= inv; v.w *= inv;
                } else if (gk < Ktot) {
                    v = *(const float4*)(Ae + (size_t)grow * 128 + (gk - KF - 128));
                }
                va[j] = v;
            }
        }

        // ---- MMA over this chunk ----
        const int ksteps = min(2, (Ktot - c * 32) >> 4);
#pragma unroll
        for (int ks = 0; ks < 2; ks++) {
            if (ks >= ksteps) break;
            uint32_t ah[4][4], al[4][4];
#pragma unroll
            for (int mt = 0; mt < 4; mt++) {
                uint32_t arow = (uint32_t)(m_base + mt * 16 + lmA_row);
                uint32_t off = (arow * A_STRIDE + ks * 16 + lmA_ko) * 2;
                LDM4(ah[mt], a_hi + off);
                LDM4(al[mt], a_lo + off);
            }
            uint32_t bhf[2][4], blf[2][4];
            const int kg = c * 32 + ks * 16;
#pragma unroll
            for (int nt2 = 0; nt2 < 2; nt2++) {
                uint32_t bn = (uint32_t)(n_base + nt2 * 16 + lmB_n);
                uint32_t off = (bn * B_STRIDE + kg + lmB_ko) * 2;
                LDM4(bhf[nt2], bs_hi + off);
                LDM4(blf[nt2], bs_lo + off);
            }
#pragma unroll
            for (int mt = 0; mt < 4; mt++) {
#pragma unroll
                for (int nt = 0; nt < 4; nt++) {
                    uint32_t bh0 = bhf[nt >> 1][(nt & 1) * 2];
                    uint32_t bh1 = bhf[nt >> 1][(nt & 1) * 2 + 1];
                    uint32_t bl0 = blf[nt >> 1][(nt & 1) * 2];
                    uint32_t bl1 = blf[nt >> 1][(nt & 1) * 2 + 1];
                    MMA16816(acc[mt][nt], ah[mt], bh0, bh1);
                    MMA16816(acc[mt][nt], al[mt], bh0, bh1);
                    MMA16816(acc[mt][nt], ah[mt], bl0, bl1);
                }
            }
        }
        __syncthreads();
    }

    // ---- epilogue ----
#pragma unroll
    for (int mt = 0; mt < 4; mt++) {
        int row_a = row0 + m_base + mt * 16 + (lane >> 2);
        int row_b = row_a + 8;
        const float* qa = nullptr;
        const float* qb = nullptr;
        if (Q) {
            if (row_a < M) qa = Q + (size_t)qidx[row_a] * 128;
            if (row_b < M) qb = Q + (size_t)qidx[row_b] * 128;
        }
#pragma unroll
        for (int nt = 0; nt < 4; nt++) {
            int col = n_base + nt * 8 + (lane & 3) * 2;
            float b0 = 0.f, b1 = 0.f;
            if (bias) { b0 = bias[col]; b1 = bias[col + 1]; }
            if (row_a < M) {
                float v0 = acc[mt][nt][0] + b0;
                float v1 = acc[mt][nt][1] + b1;
                if (qa) { v0 += qa[col]; v1 += qa[col + 1]; }
                if (act) { v0 = lrelu(v0); v1 = lrelu(v1); }
                float2* p = (float2*)(out + (size_t)row_a * 128 + col);
                *p = make_float2(v0, v1);
            }
            if (row_b < M) {
                float v0 = acc[mt][nt][2] + b0;
                float v1 = acc[mt][nt][3] + b1;
                if (qb) { v0 += qb[col]; v1 += qb[col + 1]; }
                if (act) { v0 = lrelu(v0); v1 = lrelu(v1); }
                float2* p = (float2*)(out + (size_t)row_b * 128 + col);
                *p = make_float2(v0, v1);
            }
        }
    }
}

// ---------------- small SIMT GEMM (kept for the tiny Q precomputes) ---------
__global__ __launch_bounds__(256, 2) void fused_gemm(
    int M,
    const float* __restrict__ Ah, const float* __restrict__ Wh,
    float* __restrict__ out)
{
    __shared__ float As[64][16];
    __shared__ float Ws[16][128];

    const int t  = threadIdx.x;
    const int tx = t & 31;
    const int ty = t >> 5;
    const int row0 = blockIdx.x * 64;

    float acc[8][4];
#pragma unroll
    for (int r = 0; r < 8; r++)
        acc[r][0] = acc[r][1] = acc[r][2] = acc[r][3] = 0.f;

    const int aRow = t >> 2;
    const int aK   = (t & 3) * 4;
    const int wK   = t >> 4;
    const int wC   = (t & 15) * 8;

    int arow_g = row0 + aRow;
    if (arow_g >= M) arow_g = M - 1;

    for (int kk = 0; kk < 128; kk += 16) {
        __syncthreads();
        float4 av = *(const float4*)(Ah + (size_t)arow_g * 128 + kk + aK);
        *(float4*)&As[aRow][aK] = av;
        const float* wp = Wh + (size_t)(kk + wK) * 128 + wC;
        *(float4*)&Ws[wK][wC]     = *(const float4*)(wp);
        *(float4*)&Ws[wK][wC + 4] = *(const float4*)(wp + 4);
        __syncthreads();

#pragma unroll
        for (int k = 0; k < 16; k++) {
            float4 w = *(const float4*)&Ws[k][tx * 4];
#pragma unroll
            for (int r = 0; r < 8; r++) {
                float a = As[ty * 8 + r][k];
                acc[r][0] = fmaf(a, w.x, acc[r][0]);
                acc[r][1] = fmaf(a, w.y, acc[r][1]);
                acc[r][2] = fmaf(a, w.z, acc[r][2]);
                acc[r][3] = fmaf(a, w.w, acc[r][3]);
            }
        }
    }

#pragma unroll
    for (int r = 0; r < 8; r++) {
        int row = row0 + ty * 8 + r;
        if (row < M) {
            float4 v = make_float4(acc[r][0], acc[r][1], acc[r][2], acc[r][3]);
            *(float4*)(out + (size_t)row * 128 + tx * 4) = v;
        }
    }
}

// ---------------- edge message + scatter ------------------------------------
__global__ __launch_bounds__(256) void edge_kernel(
    int E,
    const float* __restrict__ es,
    const int*   __restrict__ src,
    const int*   __restrict__ dst,
    const float* __restrict__ P,
    const float* __restrict__ W1,
    const float* __restrict__ b,
    float* __restrict__ acc,
    float* __restrict__ cnt)
{
    const int lane = threadIdx.x & 31;
    const int c = lane * 4;

    float w[4][4], bb[4];
#pragma unroll
    for (int r = 0; r < 4; r++)
#pragma unroll
        for (int i = 0; i < 4; i++)
            w[r][i] = W1[r * 128 + c + i];
#pragma unroll
    for (int i = 0; i < 4; i++) bb[i] = b[c + i];

    int warp  = blockIdx.x * (blockDim.x >> 5) + (threadIdx.x >> 5);
    int nwarp = gridDim.x * (blockDim.x >> 5);

    for (int e = warp; e < E; e += nwarp) {
        int s = src[e], d = dst[e];
        float4 ev = *(const float4*)(es + (size_t)e * 4);
        float4 p  = *(const float4*)(P + (size_t)s * 128 + c);
        float m0 = bb[0], m1 = bb[1], m2 = bb[2], m3 = bb[3];
        m0 = fmaf(ev.x, w[0][0], m0); m0 = fmaf(ev.y, w[1][0], m0);
        m0 = fmaf(ev.z, w[2][0], m0); m0 = fmaf(ev.w, w[3][0], m0);
        m1 = fmaf(ev.x, w[0][1], m1); m1 = fmaf(ev.y, w[1][1], m1);
        m1 = fmaf(ev.z, w[2][1], m1); m1 = fmaf(ev.w, w[3][1], m1);
        m2 = fmaf(ev.x, w[0][2], m2); m2 = fmaf(ev.y, w[1][2], m2);
        m2 = fmaf(ev.z, w[2][2], m2); m2 = fmaf(ev.w, w[3][2], m2);
        m3 = fmaf(ev.x, w[0][3], m3); m3 = fmaf(ev.y, w[1][3], m3);
        m3 = fmaf(ev.z, w[2][3], m3); m3 = fmaf(ev.w, w[3][3], m3);
        m0 = lrelu(m0 + p.x);
        m1 = lrelu(m1 + p.y);
        m2 = lrelu(m2 + p.z);
        m3 = lrelu(m3 + p.w);

        float* ap = acc + (size_t)d * 128 + c;
        asm volatile("red.global.add.v4.f32 [%0], {%1, %2, %3, %4};"
                     :: "l"(ap), "f"(m0), "f"(m1), "f"(m2), "f"(m3)
                     : "memory");
        if (lane == 0) atomicAdd(cnt + d, 1.f);
    }
}

// ---------------- segment mean into NU=64 contexts --------------------------
__global__ __launch_bounds__(128) void seg_mean_ctx(
    const float* __restrict__ srcm, const int* __restrict__ ids, int n,
    float* __restrict__ acc, float* __restrict__ cntp)
{
    __shared__ float sacc[64 * 128];
    __shared__ float scnt[64];
    const int t = threadIdx.x;
    for (int i = t; i < 64 * 128; i += 128) sacc[i] = 0.f;
    if (t < 64) scnt[t] = 0.f;
    __syncthreads();

    for (long r0 = (long)blockIdx.x * 4; r0 < n; r0 += (long)gridDim.x * 4) {
        float v[4]; int id[4]; int k = 0;
#pragma unroll
        for (int u = 0; u < 4; u++) {
            long r = r0 + u;
            if (r < n) {
                id[k] = ids[r];
                v[k]  = srcm[(size_t)r * 128 + t];
                k++;
            }
        }
        for (int u = 0; u < k; u++) {
            sacc[id[u] * 128 + t] += v[u];
            if (t == 0) scnt[id[u]] += 1.f;
        }
    }
    __syncthreads();
    for (int i = t; i < 64 * 128; i += 128) atomicAdd(&acc[i], sacc[i]);
    if (t < 64) atomicAdd(&cntp[t], scnt[t]);
}

// ---------------- context update (64 rows, K=400) ---------------------------
__global__ __launch_bounds__(128) void ctx_update(
    const float* __restrict__ ctx_feats,
    const float* __restrict__ ctx_emb,
    const float* __restrict__ acc,
    const float* __restrict__ cntp,
    const float* __restrict__ Wu,
    const float* __restrict__ bu,
    float* __restrict__ out)
{
    const int u = blockIdx.x;
    const int t = threadIdx.x;
    __shared__ float a[400];

    if (t < 16) a[t] = ctx_feats[u * 16 + t];
    float cc = fmaxf(cntp[u], 1.f);
    float cv = fmaxf(cntp[64 + u], 1.f);
    a[16 + t]  = acc[u * 128 + t] / cc;
    a[144 + t] = acc[64 * 128 + u * 128 + t] / cv;
    a[272 + t] = ctx_emb[u * 128 + t];
    __syncthreads();

    float s = bu[t];
    for (int k = 0; k < 400; k++) s = fmaf(a[k], Wu[k * 128 + t], s);
    out[(size_t)u * 128 + t] = lrelu(s);
}

// ---------------- launch ----------------------------------------------------
extern "C" void kernel_launch(void* const* d_in, const int* in_sizes, int n_in,
                              void* d_out, int out_size)
{
    const float* var_emb      = (const float*)d_in[0];
    const float* clause_emb   = (const float*)d_in[1];
    const float* ctx_emb      = (const float*)d_in[2];
    const float* var_feats    = (const float*)d_in[3];
    const float* clause_feats = (const float*)d_in[4];
    const float* ctx_feats    = (const float*)d_in[5];
    const float* edge_sat_vc  = (const float*)d_in[6];
    const float* edge_sat_cv  = (const float*)d_in[7];
    const float* W_vc         = (const float*)d_in[8];
    const float* b_vc         = (const float*)d_in[9];
    const float* W_cv         = (const float*)d_in[10];
    const float* b_cv         = (const float*)d_in[11];
    const float* W_c          = (const float*)d_in[12];
    const float* b_c          = (const float*)d_in[13];
    const float* W_v          = (const float*)d_in[14];
    const float* b_v          = (const float*)d_in[15];
    const float* W_u          = (const float*)d_in[16];
    const float* b_u          = (const float*)d_in[17];
    const int* assigns_src    = (const int*)d_in[18];
    const int* assigns_dst    = (const int*)d_in[19];
    const int* contains_src   = (const int*)d_in[20];
    const int* contains_dst   = (const int*)d_in[21];
    const int* var_ctx        = (const int*)d_in[22];
    const int* clause_ctx     = (const int*)d_in[23];

    const int NV = in_sizes[0] / C_D;
    const int NC = in_sizes[1] / C_D;
    const int E  = in_sizes[18];

    float *hc, *hv, *cc, *cv, *Pv, *Pc, *Qc, *Qv, *cacc, *ccnt;
    cudaGetSymbolAddress((void**)&hc,   g_hc);
    cudaGetSymbolAddress((void**)&hv,   g_hv);
    cudaGetSymbolAddress((void**)&cc,   g_cnt_c);
    cudaGetSymbolAddress((void**)&cv,   g_cnt_v);
    cudaGetSymbolAddress((void**)&Pv,   g_Pv);
    cudaGetSymbolAddress((void**)&Pc,   g_Pc);
    cudaGetSymbolAddress((void**)&Qc,   g_Qc);
    cudaGetSymbolAddress((void**)&Qv,   g_Qv);
    cudaGetSymbolAddress((void**)&cacc, g_ctx_acc);
    cudaGetSymbolAddress((void**)&ccnt, g_ctx_cnt);

    __nv_bfloat16 *Bvc_h, *Bvc_l, *Bcv_h, *Bcv_l, *Bc_h, *Bc_l, *Bv_h, *Bv_l;
    cudaGetSymbolAddress((void**)&Bvc_h, g_Bvc_h);
    cudaGetSymbolAddress((void**)&Bvc_l, g_Bvc_l);
    cudaGetSymbolAddress((void**)&Bcv_h, g_Bcv_h);
    cudaGetSymbolAddress((void**)&Bcv_l, g_Bcv_l);
    cudaGetSymbolAddress((void**)&Bc_h,  g_Bc_h);
    cudaGetSymbolAddress((void**)&Bc_l,  g_Bc_l);
    cudaGetSymbolAddress((void**)&Bv_h,  g_Bv_h);
    cudaGetSymbolAddress((void**)&Bv_l,  g_Bv_l);

    float* out = (float*)d_out;

    cudaFuncSetAttribute(tc_gemm, cudaFuncAttributeMaxDynamicSharedMemorySize,
                         SMEM_TOTAL_TC);

    // 0. zero all accumulators (one launch)
    zero_all<<<2048, 256>>>(
        (float4*)hc,   (long)NC * C_D / 4,
        (float4*)hv,   (long)NV * C_D / 4,
        (float4*)cc,   (long)NC / 4,
        (float4*)cv,   (long)NV / 4,
        (float4*)cacc, (long)(2 * C_NU * C_D) / 4,
        (float4*)ccnt, (long)(2 * C_NU) / 4);

    // 1. weight transpose + split
    wprep<<<(102400 + 255) / 256, 256>>>(W_vc, W_cv, W_c, W_v);

    // 2. P_v = var_emb @ W_vc[4:132]   (HMMA)
    tc_gemm<<<(NV + 127) / 128, 256, SMEM_TOTAL_TC>>>(
        NV, nullptr, 0, var_emb, nullptr, nullptr,
        Bvc_h, Bvc_l, 128, nullptr, nullptr, nullptr, 0, Pv);
    // 3. P_c = clause_emb @ W_cv[4:132] (HMMA)
    tc_gemm<<<(NC + 127) / 128, 256, SMEM_TOTAL_TC>>>(
        NC, nullptr, 0, clause_emb, nullptr, nullptr,
        Bcv_h, Bcv_l, 128, nullptr, nullptr, nullptr, 0, Pc);

    // 4. Q_c = ctx_emb @ W_c[144:272]  (tiny, SIMT)
    fused_gemm<<<1, 256>>>(C_NU, ctx_emb, W_c + 144 * C_D, Qc);

    // 5. edge messages: var -> clause   <-- ncu -s 5 -c 1 captures this
    edge_kernel<<<4096, 256>>>(E, edge_sat_vc, assigns_src, assigns_dst,
                               Pv, W_vc, b_vc, hc, cc);
    // 6. edge messages: clause -> var
    edge_kernel<<<4096, 256>>>(E, edge_sat_cv, contains_src, contains_dst,
                               Pc, W_cv, b_cv, hv, cv);

    // 7. Q_v = ctx_emb @ W_v[144:272]
    fused_gemm<<<1, 256>>>(C_NU, ctx_emb, W_v + 144 * C_D, Qv);

    // 8. new_clause (HMMA, fused epilogue) -> out rows [0, NC)
    tc_gemm<<<(NC + 127) / 128, 256, SMEM_TOTAL_TC>>>(
        NC, clause_feats, 16, hc, cc, clause_emb,
        Bc_h, Bc_l, 272, b_c, Qc, clause_ctx, 1, out);
    // 9. new_var (HMMA) -> out rows [NC, NC+NV)
    tc_gemm<<<(NV + 127) / 128, 256, SMEM_TOTAL_TC>>>(
        NV, var_feats, 16, hv, cv, var_emb,
        Bv_h, Bv_l, 272, b_v, Qv, var_ctx, 1, out + (size_t)NC * C_D);

    // 10-11. context means over the NEW embeddings
    seg_mean_ctx<<<1024, 128>>>(out, clause_ctx, NC, cacc, ccnt);
    seg_mean_ctx<<<1024, 128>>>(out + (size_t)NC * C_D, var_ctx, NV,
                                cacc + C_NU * C_D, ccnt + C_NU);

    // 12. context update: rows [NC+NV, NC+NV+NU)
    ctx_update<<<C_NU, 128>>>(ctx_feats, ctx_emb, cacc, ccnt, W_u, b_u,
                              out + (size_t)(NC + NV) * C_D);
}

// round 4
// speedup vs baseline: 1.2225x; 1.0961x over previous
#include <cuda_runtime.h>
#include <cuda_bf16.h>
#include <cstdint>

// Problem constants (fixed by the dataset)
#define C_NV 100000
#define C_NC 400000
#define C_NU 64
#define C_E  1200000
#define C_D  128

// ---------------- scratch (device globals; no allocation allowed) ----------
__device__ float g_hc[(size_t)C_NC * C_D];     // clause message accumulators
__device__ float g_hv[(size_t)C_NV * C_D];     // var message accumulators
__device__ float g_cnt_c[C_NC];
__device__ float g_cnt_v[C_NV];
__device__ float g_Pv[(size_t)C_NV * C_D];     // var_emb @ W_vc[4:132]
__device__ float g_Pc[(size_t)C_NC * C_D];     // clause_emb @ W_cv[4:132]
__device__ float g_Qc[C_NU * C_D];             // ctx_emb @ W_c[144:272]
__device__ float g_Qv[C_NU * C_D];             // ctx_emb @ W_v[144:272]
__device__ float g_ctx_acc[2 * C_NU * C_D];    // [clause sums | var sums]
__device__ float g_ctx_cnt[2 * C_NU];

// Transposed + bf16-split weight buffers: layout [n (0..127)][k (0..K-1)]
__device__ __align__(16) __nv_bfloat16 g_Bvc_h[128 * 128];
__device__ __align__(16) __nv_bfloat16 g_Bvc_l[128 * 128];
__device__ __align__(16) __nv_bfloat16 g_Bcv_h[128 * 128];
__device__ __align__(16) __nv_bfloat16 g_Bcv_l[128 * 128];
__device__ __align__(16) __nv_bfloat16 g_Bc_h[128 * 272];
__device__ __align__(16) __nv_bfloat16 g_Bc_l[128 * 272];
__device__ __align__(16) __nv_bfloat16 g_Bv_h[128 * 272];
__device__ __align__(16) __nv_bfloat16 g_Bv_l[128 * 272];

static __device__ __forceinline__ float lrelu(float x) {
    return x >= 0.f ? x : 0.1f * x;
}

static __device__ __forceinline__ uint32_t smem_u32(const void* p) {
    uint32_t a;
    asm("{ .reg .u64 t; cvta.to.shared.u64 t, %1; cvt.u32.u64 %0, t; }"
        : "=r"(a) : "l"(p));
    return a;
}

// ldmatrix x4 (non-transposed)
#define LDM4(d, addr)                                                          \
    asm volatile(                                                              \
        "ldmatrix.sync.aligned.m8n8.x4.shared.b16 {%0,%1,%2,%3}, [%4];"        \
        : "=r"((d)[0]), "=r"((d)[1]), "=r"((d)[2]), "=r"((d)[3])               \
        : "r"(addr))

// mma.sync m16n8k16 bf16 -> fp32
#define MMA16816(c, a, b0, b1)                                                 \
    asm volatile(                                                              \
        "mma.sync.aligned.m16n8k16.row.col.f32.bf16.bf16.f32 "                 \
        "{%0,%1,%2,%3}, {%4,%5,%6,%7}, {%8,%9}, {%0,%1,%2,%3};"                \
        : "+f"((c)[0]), "+f"((c)[1]), "+f"((c)[2]), "+f"((c)[3])               \
        : "r"((a)[0]), "r"((a)[1]), "r"((a)[2]), "r"((a)[3]),                  \
          "r"(b0), "r"(b1))

#define CP_ASYNC16(dst, src, sz)                                               \
    asm volatile("cp.async.cg.shared.global [%0], [%1], 16, %2;"               \
                 :: "r"(dst), "l"(src), "r"(sz))
#define CP_COMMIT() asm volatile("cp.async.commit_group;" ::: "memory")
#define CP_WAIT(n)  asm volatile("cp.async.wait_group %0;" :: "n"(n) : "memory")

// fp32 -> packed (bf16 hi pair, bf16 lo pair)
static __device__ __forceinline__ void split2(
    float a, float b, uint32_t& hi, uint32_t& lo)
{
    __nv_bfloat16 ah = __float2bfloat16(a);
    __nv_bfloat16 bh = __float2bfloat16(b);
    float ar = a - __bfloat162float(ah);
    float br = b - __bfloat162float(bh);
    __nv_bfloat16 al = __float2bfloat16(ar);
    __nv_bfloat16 bl = __float2bfloat16(br);
    hi = (uint32_t)__bfloat16_as_ushort(ah) |
         ((uint32_t)__bfloat16_as_ushort(bh) << 16);
    lo = (uint32_t)__bfloat16_as_ushort(al) |
         ((uint32_t)__bfloat16_as_ushort(bl) << 16);
}

// ---------------- zero all accumulators (single launch) --------------------
__global__ void zero_all(float4* hc, long n0, float4* hv, long n1,
                         float4* cc, long n2, float4* cv, long n3,
                         float4* cacc, long n4, float4* ccnt, long n5)
{
    long i = (long)blockIdx.x * blockDim.x + threadIdx.x;
    long stride = (long)gridDim.x * blockDim.x;
    float4 z = make_float4(0.f, 0.f, 0.f, 0.f);
    long t01 = n0 + n1, t02 = t01 + n2, t03 = t02 + n3, t04 = t03 + n4;
    long tot = t04 + n5;
    for (; i < tot; i += stride) {
        if (i < n0)       hc[i] = z;
        else if (i < t01) hv[i - n0] = z;
        else if (i < t02) cc[i - t01] = z;
        else if (i < t03) cv[i - t02] = z;
        else if (i < t04) cacc[i - t03] = z;
        else              ccnt[i - t04] = z;
    }
}

// ---------------- weight transpose + bf16 hi/lo split -----------------------
__global__ void wprep(const float* __restrict__ Wvc, const float* __restrict__ Wcv,
                      const float* __restrict__ Wc,  const float* __restrict__ Wv)
{
    int i = blockIdx.x * blockDim.x + threadIdx.x;
    if (i >= 102400) return;
    float w;
    __nv_bfloat16 *dh, *dl;
    int di;
    if (i < 16384) {                       // vc: K=128, W rows 4..131
        int n = i >> 7, k = i & 127;
        w = Wvc[(4 + k) * 128 + n];
        dh = g_Bvc_h; dl = g_Bvc_l; di = n * 128 + k;
    } else if (i < 32768) {                // cv: K=128, W rows 4..131
        int j = i - 16384;
        int n = j >> 7, k = j & 127;
        w = Wcv[(4 + k) * 128 + n];
        dh = g_Bcv_h; dl = g_Bcv_l; di = n * 128 + k;
    } else if (i < 67584) {                // c: K=272, W rows {0..143, 272..399}
        int j = i - 32768;
        int n = j / 272, k = j % 272;
        int kk = (k < 144) ? k : k + 128;
        w = Wc[kk * 128 + n];
        dh = g_Bc_h; dl = g_Bc_l; di = n * 272 + k;
    } else {                               // v: K=272
        int j = i - 67584;
        int n = j / 272, k = j % 272;
        int kk = (k < 144) ? k : k + 128;
        w = Wv[kk * 128 + n];
        dh = g_Bv_h; dl = g_Bv_l; di = n * 272 + k;
    }
    __nv_bfloat16 h = __float2bfloat16(w);
    float r = w - __bfloat162float(h);
    dh[di] = h;
    dl[di] = __float2bfloat16(r);
}

// ---------------- HMMA GEMM (bf16x3, pipelined, 2 CTAs/SM) ------------------
// out[row, col0:col0+64] = act([Af | Ah/max(cnt,1) | Ae] @ B^T + bias + Q[qidx])
// Tile: 128(M) x 64(N), grid.y = 2 covers N=128. BK=32.
// A: LDG reg-prefetch -> convert/split -> 2-buffer smem.
// B: cp.async (zero-filled tail) -> 3-stage smem ring.
// One __syncthreads per chunk.
#define BK 32
#define A_ST 40                            // A smem row stride (elements)
#define B_ST 40                            // B smem row stride (elements)
#define A_HALF (128 * A_ST * 2)            // 10240 B (one of hi/lo)
#define B_HALF (64 * B_ST * 2)             // 5120 B
#define B_BASE (4 * A_HALF)                // 40960
#define SMEM_TOTAL_TC (B_BASE + 6 * B_HALF)  // 71680

__global__ __launch_bounds__(256, 2) void tc_gemm(
    int M,
    const float* __restrict__ Af, int KF,
    const float* __restrict__ Ah, const float* __restrict__ cnt,
    const float* __restrict__ Ae,
    const __nv_bfloat16* __restrict__ Bh, const __nv_bfloat16* __restrict__ Bl,
    int Ktot,
    const float* __restrict__ bias, const float* __restrict__ Q,
    const int* __restrict__ qidx, int act,
    float* __restrict__ out)
{
    extern __shared__ char smem[];
    const uint32_t sb = smem_u32(smem);
    const int tid  = threadIdx.x;
    const int wid  = tid >> 5;
    const int lane = tid & 31;

    const int row0 = blockIdx.x * 128;
    const int col0 = blockIdx.y * 64;

    // A staging assignment: row r, k-half h
    const int r = tid >> 1;
    const int h = tid & 1;
    int grow = row0 + r;
    if (grow >= M) grow = M - 1;          // clamp loads; stores guarded
    float inv = 1.f;
    if (cnt) inv = 1.f / fmaxf(cnt[grow], 1.f);

    // B cp.async assignment: row brow (n), 8-elem quad bq
    const int brow = tid >> 2;
    const int bq   = (tid & 3) * 8;
    const __nv_bfloat16* bh_row = Bh + (size_t)(col0 + brow) * Ktot;
    const __nv_bfloat16* bl_row = Bl + (size_t)(col0 + brow) * Ktot;
    const uint32_t bdst = (uint32_t)(brow * B_ST + bq) * 2;

    const int nchunks = (Ktot + BK - 1) / BK;

    auto stage_b = [&](int c) {
        int s = c % 3;
        int gk = c * BK + bq;
        int rem = Ktot - gk;
        int sz = rem >= 8 ? 16 : 0;       // Ktot and bq are multiples of 8
        int gks = (rem >= 8) ? gk : (Ktot - 8);
        uint32_t dh = sb + B_BASE + (uint32_t)s * (2 * B_HALF) + bdst;
        CP_ASYNC16(dh, bh_row + gks, sz);
        CP_ASYNC16(dh + B_HALF, bl_row + gks, sz);
    };

    auto load_a = [&](int c, float4* va) {
        int k0 = c * BK;
#pragma unroll
        for (int j = 0; j < 4; j++) {
            int gk = k0 + h * 16 + j * 4;
            float4 v = make_float4(0.f, 0.f, 0.f, 0.f);
            if (gk < KF) {
                v = *(const float4*)(Af + (size_t)grow * KF + gk);
            } else if (gk < KF + 128) {
                v = *(const float4*)(Ah + (size_t)grow * 128 + (gk - KF));
                v.x *= inv; v.y *= inv; v.z *= inv; v.w *= inv;
            } else if (gk < Ktot) {
                v = *(const float4*)(Ae + (size_t)grow * 128 + (gk - KF - 128));
            }
            va[j] = v;
        }
    };

    // warp tile: 32(m) x 32(n); warps 4(m) x 2(n)
    const int m_base = (wid & 3) * 32;
    const int n_base = (wid >> 2) * 32;
    float acc[2][4][4];
#pragma unroll
    for (int mt = 0; mt < 2; mt++)
#pragma unroll
        for (int nt = 0; nt < 4; nt++)
            acc[mt][nt][0] = acc[mt][nt][1] = acc[mt][nt][2] = acc[mt][nt][3] = 0.f;

    // ldmatrix per-lane patterns
    const int lmA_row = lane & 15;
    const int lmA_ko  = (lane >> 4) * 8;
    const int lmB_n   = (lane & 7) + ((lane >> 4) & 1) * 8;
    const int lmB_ko  = ((lane >> 3) & 1) * 8;

    // ---- prologue ----
    stage_b(0); CP_COMMIT();
    float4 va[4];
    load_a(0, va);

    for (int c = 0; c < nchunks; c++) {
        const int abuf = c & 1;
        const uint32_t a_hi = sb + (uint32_t)abuf * (2 * A_HALF);
        const uint32_t a_lo = a_hi + A_HALF;

        // convert + store staged A chunk
#pragma unroll
        for (int j = 0; j < 4; j++) {
            int col = h * 16 + j * 4;
            uint2 hiv, lov;
            split2(va[j].x, va[j].y, hiv.x, lov.x);
            split2(va[j].z, va[j].w, hiv.y, lov.y);
            uint32_t off = (uint32_t)(r * A_ST + col) * 2;
            *(uint2*)(smem + (a_hi - sb) + off) = hiv;
            *(uint2*)(smem + (a_lo - sb) + off) = lov;
        }

        // kick off next chunk's B (cp.async) and A (LDG into regs)
        if (c + 1 < nchunks) {
            stage_b(c + 1); CP_COMMIT();
            load_a(c + 1, va);
            CP_WAIT(1);                   // B(c) complete
        } else {
            CP_WAIT(0);
        }
        __syncthreads();

        const uint32_t b_hi = sb + B_BASE + (uint32_t)(c % 3) * (2 * B_HALF);
        const uint32_t b_lo = b_hi + B_HALF;

        const int ksteps = min(2, (Ktot - c * BK) >> 4);
#pragma unroll
        for (int ks = 0; ks < 2; ks++) {
            if (ks >= ksteps) break;
            uint32_t ah[2][4], al[2][4];
#pragma unroll
            for (int mt = 0; mt < 2; mt++) {
                uint32_t off =
                    (uint32_t)((m_base + mt * 16 + lmA_row) * A_ST +
                               ks * 16 + lmA_ko) * 2;
                LDM4(ah[mt], a_hi + off);
                LDM4(al[mt], a_lo + off);
            }
            uint32_t bhf[2][4], blf[2][4];
#pragma unroll
            for (int nt2 = 0; nt2 < 2; nt2++) {
                uint32_t off =
                    (uint32_t)((n_base + nt2 * 16 + lmB_n) * B_ST +
                               ks * 16 + lmB_ko) * 2;
                LDM4(bhf[nt2], b_hi + off);
                LDM4(blf[nt2], b_lo + off);
            }
#pragma unroll
            for (int mt = 0; mt < 2; mt++) {
#pragma unroll
                for (int nt = 0; nt < 4; nt++) {
                    uint32_t b0 = bhf[nt >> 1][(nt & 1) * 2];
                    uint32_t b1 = bhf[nt >> 1][(nt & 1) * 2 + 1];
                    uint32_t c0 = blf[nt >> 1][(nt & 1) * 2];
                    uint32_t c1 = blf[nt >> 1][(nt & 1) * 2 + 1];
                    MMA16816(acc[mt][nt], ah[mt], b0, b1);
                    MMA16816(acc[mt][nt], al[mt], b0, b1);
                    MMA16816(acc[mt][nt], ah[mt], c0, c1);
                }
            }
        }
        // no second sync: A double-buffer + B 3-stage ring make next-chunk
        // writes target buffers no concurrent reader can touch.
    }

    // ---- epilogue ----
#pragma unroll
    for (int mt = 0; mt < 2; mt++) {
        int row_a = row0 + m_base + mt * 16 + (lane >> 2);
        int row_b = row_a + 8;
        const float* qa = nullptr;
        const float* qb = nullptr;
        if (Q) {
            if (row_a < M) qa = Q + (size_t)qidx[row_a] * 128;
            if (row_b < M) qb = Q + (size_t)qidx[row_b] * 128;
        }
#pragma unroll
        for (int nt = 0; nt < 4; nt++) {
            int col = col0 + n_base + nt * 8 + (lane & 3) * 2;
            float b0 = 0.f, b1 = 0.f;
            if (bias) { b0 = bias[col]; b1 = bias[col + 1]; }
            if (row_a < M) {
                float v0 = acc[mt][nt][0] + b0;
                float v1 = acc[mt][nt][1] + b1;
                if (qa) { v0 += qa[col]; v1 += qa[col + 1]; }
                if (act) { v0 = lrelu(v0); v1 = lrelu(v1); }
                *(float2*)(out + (size_t)row_a * 128 + col) = make_float2(v0, v1);
            }
            if (row_b < M) {
                float v0 = acc[mt][nt][2] + b0;
                float v1 = acc[mt][nt][3] + b1;
                if (qb) { v0 += qb[col]; v1 += qb[col + 1]; }
                if (act) { v0 = lrelu(v0); v1 = lrelu(v1); }
                *(float2*)(out + (size_t)row_b * 128 + col) = make_float2(v0, v1);
            }
        }
    }
}

// ---------------- small SIMT GEMM (tiny Q precomputes, M=64,K=128) ----------
__global__ __launch_bounds__(256, 2) void fused_gemm(
    int M,
    const float* __restrict__ Ah, const float* __restrict__ Wh,
    float* __restrict__ out)
{
    __shared__ float As[64][16];
    __shared__ float Ws[16][128];

    const int t  = threadIdx.x;
    const int tx = t & 31;
    const int ty = t >> 5;
    const int row0 = blockIdx.x * 64;

    float acc[8][4];
#pragma unroll
    for (int r = 0; r < 8; r++)
        acc[r][0] = acc[r][1] = acc[r][2] = acc[r][3] = 0.f;

    const int aRow = t >> 2;
    const int aK   = (t & 3) * 4;
    const int wK   = t >> 4;
    const int wC   = (t & 15) * 8;

    int arow_g = row0 + aRow;
    if (arow_g >= M) arow_g = M - 1;

    for (int kk = 0; kk < 128; kk += 16) {
        __syncthreads();
        float4 av = *(const float4*)(Ah + (size_t)arow_g * 128 + kk + aK);
        *(float4*)&As[aRow][aK] = av;
        const float* wp = Wh + (size_t)(kk + wK) * 128 + wC;
        *(float4*)&Ws[wK][wC]     = *(const float4*)(wp);
        *(float4*)&Ws[wK][wC + 4] = *(const float4*)(wp + 4);
        __syncthreads();

#pragma unroll
        for (int k = 0; k < 16; k++) {
            float4 w = *(const float4*)&Ws[k][tx * 4];
#pragma unroll
            for (int r = 0; r < 8; r++) {
                float a = As[ty * 8 + r][k];
                acc[r][0] = fmaf(a, w.x, acc[r][0]);
                acc[r][1] = fmaf(a, w.y, acc[r][1]);
                acc[r][2] = fmaf(a, w.z, acc[r][2]);
                acc[r][3] = fmaf(a, w.w, acc[r][3]);
            }
        }
    }

#pragma unroll
    for (int r = 0; r < 8; r++) {
        int row = row0 + ty * 8 + r;
        if (row < M) {
            float4 v = make_float4(acc[r][0], acc[r][1], acc[r][2], acc[r][3]);
            *(float4*)(out + (size_t)row * 128 + tx * 4) = v;
        }
    }
}

// ---------------- edge message + scatter ------------------------------------
__global__ __launch_bounds__(256) void edge_kernel(
    int E,
    const float* __restrict__ es,
    const int*   __restrict__ src,
    const int*   __restrict__ dst,
    const float* __restrict__ P,
    const float* __restrict__ W1,
    const float* __restrict__ b,
    float* __restrict__ acc,
    float* __restrict__ cnt)
{
    const int lane = threadIdx.x & 31;
    const int c = lane * 4;

    float w[4][4], bb[4];
#pragma unroll
    for (int r = 0; r < 4; r++)
#pragma unroll
        for (int i = 0; i < 4; i++)
            w[r][i] = W1[r * 128 + c + i];
#pragma unroll
    for (int i = 0; i < 4; i++) bb[i] = b[c + i];

    int warp  = blockIdx.x * (blockDim.x >> 5) + (threadIdx.x >> 5);
    int nwarp = gridDim.x * (blockDim.x >> 5);

    for (int e = warp; e < E; e += nwarp) {
        int s = src[e], d = dst[e];
        float4 ev = *(const float4*)(es + (size_t)e * 4);
        float4 p  = *(const float4*)(P + (size_t)s * 128 + c);
        float m0 = bb[0], m1 = bb[1], m2 = bb[2], m3 = bb[3];
        m0 = fmaf(ev.x, w[0][0], m0); m0 = fmaf(ev.y, w[1][0], m0);
        m0 = fmaf(ev.z, w[2][0], m0); m0 = fmaf(ev.w, w[3][0], m0);
        m1 = fmaf(ev.x, w[0][1], m1); m1 = fmaf(ev.y, w[1][1], m1);
        m1 = fmaf(ev.z, w[2][1], m1); m1 = fmaf(ev.w, w[3][1], m1);
        m2 = fmaf(ev.x, w[0][2], m2); m2 = fmaf(ev.y, w[1][2], m2);
        m2 = fmaf(ev.z, w[2][2], m2); m2 = fmaf(ev.w, w[3][2], m2);
        m3 = fmaf(ev.x, w[0][3], m3); m3 = fmaf(ev.y, w[1][3], m3);
        m3 = fmaf(ev.z, w[2][3], m3); m3 = fmaf(ev.w, w[3][3], m3);
        m0 = lrelu(m0 + p.x);
        m1 = lrelu(m1 + p.y);
        m2 = lrelu(m2 + p.z);
        m3 = lrelu(m3 + p.w);

        float* ap = acc + (size_t)d * 128 + c;
        asm volatile("red.global.add.v4.f32 [%0], {%1, %2, %3, %4};"
                     :: "l"(ap), "f"(m0), "f"(m1), "f"(m2), "f"(m3)
                     : "memory");
        if (lane == 0) atomicAdd(cnt + d, 1.f);
    }
}

// ---------------- segment mean into NU=64 contexts --------------------------
__global__ __launch_bounds__(128) void seg_mean_ctx(
    const float* __restrict__ srcm, const int* __restrict__ ids, int n,
    float* __restrict__ acc, float* __restrict__ cntp)
{
    __shared__ float sacc[64 * 128];
    __shared__ float scnt[64];
    const int t = threadIdx.x;
    for (int i = t; i < 64 * 128; i += 128) sacc[i] = 0.f;
    if (t < 64) scnt[t] = 0.f;
    __syncthreads();

    for (long r0 = (long)blockIdx.x * 4; r0 < n; r0 += (long)gridDim.x * 4) {
        float v[4]; int id[4]; int k = 0;
#pragma unroll
        for (int u = 0; u < 4; u++) {
            long r = r0 + u;
            if (r < n) {
                id[k] = ids[r];
                v[k]  = srcm[(size_t)r * 128 + t];
                k++;
            }
        }
        for (int u = 0; u < k; u++) {
            sacc[id[u] * 128 + t] += v[u];
            if (t == 0) scnt[id[u]] += 1.f;
        }
    }
    __syncthreads();
    for (int i = t; i < 64 * 128; i += 128) atomicAdd(&acc[i], sacc[i]);
    if (t < 64) atomicAdd(&cntp[t], scnt[t]);
}

// ---------------- context update (64 rows, K=400) ---------------------------
__global__ __launch_bounds__(128) void ctx_update(
    const float* __restrict__ ctx_feats,
    const float* __restrict__ ctx_emb,
    const float* __restrict__ acc,
    const float* __restrict__ cntp,
    const float* __restrict__ Wu,
    const float* __restrict__ bu,
    float* __restrict__ out)
{
    const int u = blockIdx.x;
    const int t = threadIdx.x;
    __shared__ float a[400];

    if (t < 16) a[t] = ctx_feats[u * 16 + t];
    float cc = fmaxf(cntp[u], 1.f);
    float cv = fmaxf(cntp[64 + u], 1.f);
    a[16 + t]  = acc[u * 128 + t] / cc;
    a[144 + t] = acc[64 * 128 + u * 128 + t] / cv;
    a[272 + t] = ctx_emb[u * 128 + t];
    __syncthreads();

    float s = bu[t];
    for (int k = 0; k < 400; k++) s = fmaf(a[k], Wu[k * 128 + t], s);
    out[(size_t)u * 128 + t] = lrelu(s);
}

// ---------------- launch ----------------------------------------------------
extern "C" void kernel_launch(void* const* d_in, const int* in_sizes, int n_in,
                              void* d_out, int out_size)
{
    const float* var_emb      = (const float*)d_in[0];
    const float* clause_emb   = (const float*)d_in[1];
    const float* ctx_emb      = (const float*)d_in[2];
    const float* var_feats    = (const float*)d_in[3];
    const float* clause_feats = (const float*)d_in[4];
    const float* ctx_feats    = (const float*)d_in[5];
    const float* edge_sat_vc  = (const float*)d_in[6];
    const float* edge_sat_cv  = (const float*)d_in[7];
    const float* W_vc         = (const float*)d_in[8];
    const float* b_vc         = (const float*)d_in[9];
    const float* W_cv         = (const float*)d_in[10];
    const float* b_cv         = (const float*)d_in[11];
    const float* W_c          = (const float*)d_in[12];
    const float* b_c          = (const float*)d_in[13];
    const float* W_v          = (const float*)d_in[14];
    const float* b_v          = (const float*)d_in[15];
    const float* W_u          = (const float*)d_in[16];
    const float* b_u          = (const float*)d_in[17];
    const int* assigns_src    = (const int*)d_in[18];
    const int* assigns_dst    = (const int*)d_in[19];
    const int* contains_src   = (const int*)d_in[20];
    const int* contains_dst   = (const int*)d_in[21];
    const int* var_ctx        = (const int*)d_in[22];
    const int* clause_ctx     = (const int*)d_in[23];

    const int NV = in_sizes[0] / C_D;
    const int NC = in_sizes[1] / C_D;
    const int E  = in_sizes[18];

    float *hc, *hv, *cc, *cv, *Pv, *Pc, *Qc, *Qv, *cacc, *ccnt;
    cudaGetSymbolAddress((void**)&hc,   g_hc);
    cudaGetSymbolAddress((void**)&hv,   g_hv);
    cudaGetSymbolAddress((void**)&cc,   g_cnt_c);
    cudaGetSymbolAddress((void**)&cv,   g_cnt_v);
    cudaGetSymbolAddress((void**)&Pv,   g_Pv);
    cudaGetSymbolAddress((void**)&Pc,   g_Pc);
    cudaGetSymbolAddress((void**)&Qc,   g_Qc);
    cudaGetSymbolAddress((void**)&Qv,   g_Qv);
    cudaGetSymbolAddress((void**)&cacc, g_ctx_acc);
    cudaGetSymbolAddress((void**)&ccnt, g_ctx_cnt);

    __nv_bfloat16 *Bvc_h, *Bvc_l, *Bcv_h, *Bcv_l, *Bc_h, *Bc_l, *Bv_h, *Bv_l;
    cudaGetSymbolAddress((void**)&Bvc_h, g_Bvc_h);
    cudaGetSymbolAddress((void**)&Bvc_l, g_Bvc_l);
    cudaGetSymbolAddress((void**)&Bcv_h, g_Bcv_h);
    cudaGetSymbolAddress((void**)&Bcv_l, g_Bcv_l);
    cudaGetSymbolAddress((void**)&Bc_h,  g_Bc_h);
    cudaGetSymbolAddress((void**)&Bc_l,  g_Bc_l);
    cudaGetSymbolAddress((void**)&Bv_h,  g_Bv_h);
    cudaGetSymbolAddress((void**)&Bv_l,  g_Bv_l);

    float* out = (float*)d_out;

    cudaFuncSetAttribute(tc_gemm, cudaFuncAttributeMaxDynamicSharedMemorySize,
                         SMEM_TOTAL_TC);

    // 0. zero all accumulators (one launch)
    zero_all<<<2048, 256>>>(
        (float4*)hc,   (long)NC * C_D / 4,
        (float4*)hv,   (long)NV * C_D / 4,
        (float4*)cc,   (long)NC / 4,
        (float4*)cv,   (long)NV / 4,
        (float4*)cacc, (long)(2 * C_NU * C_D) / 4,
        (float4*)ccnt, (long)(2 * C_NU) / 4);

    // 1. weight transpose + split
    wprep<<<(102400 + 255) / 256, 256>>>(W_vc, W_cv, W_c, W_v);

    // 2. P_v = var_emb @ W_vc[4:132]   (HMMA)
    tc_gemm<<<dim3((NV + 127) / 128, 2), 256, SMEM_TOTAL_TC>>>(
        NV, nullptr, 0, var_emb, nullptr, nullptr,
        Bvc_h, Bvc_l, 128, nullptr, nullptr, nullptr, 0, Pv);
    // 3. P_c = clause_emb @ W_cv[4:132] (HMMA)
    tc_gemm<<<dim3((NC + 127) / 128, 2), 256, SMEM_TOTAL_TC>>>(
        NC, nullptr, 0, clause_emb, nullptr, nullptr,
        Bcv_h, Bcv_l, 128, nullptr, nullptr, nullptr, 0, Pc);

    // 4. Q_c = ctx_emb @ W_c[144:272]  (tiny, SIMT)
    fused_gemm<<<1, 256>>>(C_NU, ctx_emb, W_c + 144 * C_D, Qc);

    // 5. edge messages: var -> clause   <-- ncu -s 5 -c 1 lands here
    edge_kernel<<<4096, 256>>>(E, edge_sat_vc, assigns_src, assigns_dst,
                               Pv, W_vc, b_vc, hc, cc);
    // 6. edge messages: clause -> var
    edge_kernel<<<4096, 256>>>(E, edge_sat_cv, contains_src, contains_dst,
                               Pc, W_cv, b_cv, hv, cv);

    // 7. Q_v = ctx_emb @ W_v[144:272]
    fused_gemm<<<1, 256>>>(C_NU, ctx_emb, W_v + 144 * C_D, Qv);

    // 8. new_clause (HMMA, fused epilogue) -> out rows [0, NC)
    tc_gemm<<<dim3((NC + 127) / 128, 2), 256, SMEM_TOTAL_TC>>>(
        NC, clause_feats, 16, hc, cc, clause_emb,
        Bc_h, Bc_l, 272, b_c, Qc, clause_ctx, 1, out);
    // 9. new_var (HMMA) -> out rows [NC, NC+NV)
    tc_gemm<<<dim3((NV + 127) / 128, 2), 256, SMEM_TOTAL_TC>>>(
        NV, var_feats, 16, hv, cv, var_emb,
        Bv_h, Bv_l, 272, b_v, Qv, var_ctx, 1, out + (size_t)NC * C_D);

    // 10-11. context means over the NEW embeddings
    seg_mean_ctx<<<1024, 128>>>(out, clause_ctx, NC, cacc, ccnt);
    seg_mean_ctx<<<1024, 128>>>(out + (size_t)NC * C_D, var_ctx, NV,
                                cacc + C_NU * C_D, ccnt + C_NU);

    // 12. context update: rows [NC+NV, NC+NV+NU)
    ctx_update<<<C_NU, 128>>>(ctx_feats, ctx_emb, cacc, ccnt, W_u, b_u,
                              out + (size_t)(NC + NV) * C_D);
}

// round 5
// speedup vs baseline: 1.2539x; 1.0257x over previous
#include <cuda_runtime.h>
#include <cuda_bf16.h>
#include <cstdint>

// Problem constants (fixed by the dataset)
#define C_NV 100000
#define C_NC 400000
#define C_NU 64
#define C_E  1200000
#define C_D  128
#define C_NN (C_NC + C_NV)          // concatenated node count for degree/scan

// ---------------- scratch (device globals; no allocation allowed) ----------
__device__ float g_hc[(size_t)C_NC * C_D];     // clause message means
__device__ float g_hv[(size_t)C_NV * C_D];     // var message means
__device__ float g_Pv[(size_t)C_NV * C_D];     // var_emb @ W_vc[4:132]
__device__ float g_Pc[(size_t)C_NC * C_D];     // clause_emb @ W_cv[4:132]
__device__ float g_Qc[C_NU * C_D];             // ctx_emb @ W_c[144:272]
__device__ float g_Qv[C_NU * C_D];             // ctx_emb @ W_v[144:272]
__device__ float g_ctx_acc[2 * C_NU * C_D];    // [clause sums | var sums]
__device__ float g_ctx_cnt[2 * C_NU];

// CSR edge binning
__device__ int   g_deg[C_NN];                  // degrees -> exclusive scan (base)
__device__ int   g_fill[C_NN];                 // scatter cursors (== deg after)
__device__ int   g_bsum[256];                  // scan block sums
__device__ int   g_ssrc1[C_E];                 // dir1 (var->clause) sorted src
__device__ int   g_ssrc2[C_E];                 // dir2 (clause->var) sorted src
__device__ __align__(16) float g_ses1[(size_t)C_E * 4];
__device__ __align__(16) float g_ses2[(size_t)C_E * 4];

// Transposed + bf16-split weight buffers: layout [n (0..127)][k (0..K-1)]
__device__ __align__(16) __nv_bfloat16 g_Bvc_h[128 * 128];
__device__ __align__(16) __nv_bfloat16 g_Bvc_l[128 * 128];
__device__ __align__(16) __nv_bfloat16 g_Bcv_h[128 * 128];
__device__ __align__(16) __nv_bfloat16 g_Bcv_l[128 * 128];
__device__ __align__(16) __nv_bfloat16 g_Bc_h[128 * 272];
__device__ __align__(16) __nv_bfloat16 g_Bc_l[128 * 272];
__device__ __align__(16) __nv_bfloat16 g_Bv_h[128 * 272];
__device__ __align__(16) __nv_bfloat16 g_Bv_l[128 * 272];

static __device__ __forceinline__ float lrelu(float x) {
    return x >= 0.f ? x : 0.1f * x;
}

static __device__ __forceinline__ uint32_t smem_u32(const void* p) {
    uint32_t a;
    asm("{ .reg .u64 t; cvta.to.shared.u64 t, %1; cvt.u32.u64 %0, t; }"
        : "=r"(a) : "l"(p));
    return a;
}

// ldmatrix x4 (non-transposed)
#define LDM4(d, addr)                                                          \
    asm volatile(                                                              \
        "ldmatrix.sync.aligned.m8n8.x4.shared.b16 {%0,%1,%2,%3}, [%4];"        \
        : "=r"((d)[0]), "=r"((d)[1]), "=r"((d)[2]), "=r"((d)[3])               \
        : "r"(addr))

// mma.sync m16n8k16 bf16 -> fp32
#define MMA16816(c, a, b0, b1)                                                 \
    asm volatile(                                                              \
        "mma.sync.aligned.m16n8k16.row.col.f32.bf16.bf16.f32 "                 \
        "{%0,%1,%2,%3}, {%4,%5,%6,%7}, {%8,%9}, {%0,%1,%2,%3};"                \
        : "+f"((c)[0]), "+f"((c)[1]), "+f"((c)[2]), "+f"((c)[3])               \
        : "r"((a)[0]), "r"((a)[1]), "r"((a)[2]), "r"((a)[3]),                  \
          "r"(b0), "r"(b1))

#define CP_ASYNC16(dst, src, sz)                                               \
    asm volatile("cp.async.cg.shared.global [%0], [%1], 16, %2;"               \
                 :: "r"(dst), "l"(src), "r"(sz))
#define CP_COMMIT() asm volatile("cp.async.commit_group;" ::: "memory")
#define CP_WAIT(n)  asm volatile("cp.async.wait_group %0;" :: "n"(n) : "memory")

// fp32 -> packed (bf16 hi pair, bf16 lo pair)
static __device__ __forceinline__ void split2(
    float a, float b, uint32_t& hi, uint32_t& lo)
{
    __nv_bfloat16 ah = __float2bfloat16(a);
    __nv_bfloat16 bh = __float2bfloat16(b);
    float ar = a - __bfloat162float(ah);
    float br = b - __bfloat162float(bh);
    __nv_bfloat16 al = __float2bfloat16(ar);
    __nv_bfloat16 bl = __float2bfloat16(br);
    hi = (uint32_t)__bfloat16_as_ushort(ah) |
         ((uint32_t)__bfloat16_as_ushort(bh) << 16);
    lo = (uint32_t)__bfloat16_as_ushort(al) |
         ((uint32_t)__bfloat16_as_ushort(bl) << 16);
}

// ---------------- zero small accumulators ------------------------------------
__global__ void zero_small(int* deg, int* fill, float* cacc, float* ccnt)
{
    int i = blockIdx.x * blockDim.x + threadIdx.x;
    int stride = gridDim.x * blockDim.x;
    for (int j = i; j < C_NN; j += stride) { deg[j] = 0; fill[j] = 0; }
    for (int j = i; j < 2 * C_NU * C_D; j += stride) cacc[j] = 0.f;
    if (i < 2 * C_NU) ccnt[i] = 0.f;
}

// ---------------- histogram of destinations ---------------------------------
__global__ void hist_kernel(int E, const int* __restrict__ dst1,
                            const int* __restrict__ dst2, int* __restrict__ deg)
{
    int i = blockIdx.x * blockDim.x + threadIdx.x;
    if (i < E)          atomicAdd(&deg[dst1[i]], 1);
    else if (i < 2 * E) atomicAdd(&deg[C_NC + dst2[i - E]], 1);
}

// ---------------- exclusive scan (3 kernels, 4096/block) ---------------------
__global__ void scanA(const int* __restrict__ deg, int n,
                      int* __restrict__ base, int* __restrict__ bsum)
{
    __shared__ int tsum[256];
    const int t = threadIdx.x;
    const int b0 = blockIdx.x * 4096;
    int v[16];
    int s = 0;
#pragma unroll
    for (int j = 0; j < 16; j++) {
        int idx = b0 + t * 16 + j;
        v[j] = (idx < n) ? deg[idx] : 0;
        s += v[j];
    }
    tsum[t] = s;
    __syncthreads();
    for (int off = 1; off < 256; off <<= 1) {
        int u = (t >= off) ? tsum[t - off] : 0;
        __syncthreads();
        tsum[t] += u;
        __syncthreads();
    }
    int run = tsum[t] - s;   // exclusive prefix of this thread's chunk
#pragma unroll
    for (int j = 0; j < 16; j++) {
        int idx = b0 + t * 16 + j;
        if (idx < n) base[idx] = run;
        run += v[j];
    }
    if (t == 255) bsum[blockIdx.x] = tsum[255];
}

__global__ void scanB(int* bsum, int nb)
{
    if (threadIdx.x == 0 && blockIdx.x == 0) {
        int r = 0;
        for (int i = 0; i < nb; i++) { int d = bsum[i]; bsum[i] = r; r += d; }
    }
}

__global__ void scanC(int* __restrict__ base, const int* __restrict__ bsum, int n)
{
    int i = blockIdx.x * blockDim.x + threadIdx.x;
    if (i < n) base[i] += bsum[i >> 12];
}

// ---------------- scatter edges into destination order ----------------------
__global__ void scatter_kernel(
    int E,
    const int* __restrict__ src1, const int* __restrict__ dst1,
    const float4* __restrict__ es1,
    const int* __restrict__ src2, const int* __restrict__ dst2,
    const float4* __restrict__ es2,
    const int* __restrict__ base, int* __restrict__ fill,
    int* __restrict__ ssrc1, float4* __restrict__ ses1,
    int* __restrict__ ssrc2, float4* __restrict__ ses2)
{
    int i = blockIdx.x * blockDim.x + threadIdx.x;
    if (i < E) {
        int d = dst1[i];
        int p = base[d] + atomicAdd(&fill[d], 1);
        ssrc1[p] = src1[i];
        ses1[p]  = es1[i];
    } else if (i < 2 * E) {
        int e = i - E;
        int d = C_NC + dst2[e];
        int p = base[d] + atomicAdd(&fill[d], 1) - E;   // dir2 region starts at E
        ssrc2[p] = src2[e];
        ses2[p]  = es2[e];
    }
}

// ---------------- CSR aggregate: warp per destination node ------------------
// h[node,:] = (1/max(deg,1)) * sum_j lrelu(b + es_j @ W1 + P[src_j])
__global__ __launch_bounds__(256) void agg_kernel(
    int N0, int baseoff, int posoff,
    const int* __restrict__ base, const int* __restrict__ fill,
    const int* __restrict__ ssrc, const float4* __restrict__ ses,
    const float* __restrict__ P,
    const float* __restrict__ W1, const float* __restrict__ b,
    float* __restrict__ outh)
{
    const int warp = blockIdx.x * 8 + (threadIdx.x >> 5);
    if (warp >= N0) return;
    const int lane = threadIdx.x & 31;
    const int c = lane * 4;

    float w[4][4], bb[4];
#pragma unroll
    for (int r = 0; r < 4; r++)
#pragma unroll
        for (int i = 0; i < 4; i++)
            w[r][i] = W1[r * 128 + c + i];
#pragma unroll
    for (int i = 0; i < 4; i++) bb[i] = b[c + i];

    const int start = base[baseoff + warp] - posoff;
    const int deg   = fill[baseoff + warp];

    float s0 = 0.f, s1 = 0.f, s2 = 0.f, s3 = 0.f;
    for (int j = 0; j < deg; j++) {
        int s = ssrc[start + j];
        float4 ev = ses[start + j];
        float4 p  = *(const float4*)(P + (size_t)s * 128 + c);
        float m0 = bb[0], m1 = bb[1], m2 = bb[2], m3 = bb[3];
        m0 = fmaf(ev.x, w[0][0], m0); m0 = fmaf(ev.y, w[1][0], m0);
        m0 = fmaf(ev.z, w[2][0], m0); m0 = fmaf(ev.w, w[3][0], m0);
        m1 = fmaf(ev.x, w[0][1], m1); m1 = fmaf(ev.y, w[1][1], m1);
        m1 = fmaf(ev.z, w[2][1], m1); m1 = fmaf(ev.w, w[3][1], m1);
        m2 = fmaf(ev.x, w[0][2], m2); m2 = fmaf(ev.y, w[1][2], m2);
        m2 = fmaf(ev.z, w[2][2], m2); m2 = fmaf(ev.w, w[3][2], m2);
        m3 = fmaf(ev.x, w[0][3], m3); m3 = fmaf(ev.y, w[1][3], m3);
        m3 = fmaf(ev.z, w[2][3], m3); m3 = fmaf(ev.w, w[3][3], m3);
        s0 += lrelu(m0 + p.x);
        s1 += lrelu(m1 + p.y);
        s2 += lrelu(m2 + p.z);
        s3 += lrelu(m3 + p.w);
    }
    float inv = (deg > 0) ? (1.f / (float)deg) : 0.f;
    *(float4*)(outh + (size_t)warp * 128 + c) =
        make_float4(s0 * inv, s1 * inv, s2 * inv, s3 * inv);
}

// ---------------- weight transpose + bf16 hi/lo split -----------------------
__global__ void wprep(const float* __restrict__ Wvc, const float* __restrict__ Wcv,
                      const float* __restrict__ Wc,  const float* __restrict__ Wv)
{
    int i = blockIdx.x * blockDim.x + threadIdx.x;
    if (i >= 102400) return;
    float w;
    __nv_bfloat16 *dh, *dl;
    int di;
    if (i < 16384) {                       // vc: K=128, W rows 4..131
        int n = i >> 7, k = i & 127;
        w = Wvc[(4 + k) * 128 + n];
        dh = g_Bvc_h; dl = g_Bvc_l; di = n * 128 + k;
    } else if (i < 32768) {                // cv: K=128, W rows 4..131
        int j = i - 16384;
        int n = j >> 7, k = j & 127;
        w = Wcv[(4 + k) * 128 + n];
        dh = g_Bcv_h; dl = g_Bcv_l; di = n * 128 + k;
    } else if (i < 67584) {                // c: K=272, W rows {0..143, 272..399}
        int j = i - 32768;
        int n = j / 272, k = j % 272;
        int kk = (k < 144) ? k : k + 128;
        w = Wc[kk * 128 + n];
        dh = g_Bc_h; dl = g_Bc_l; di = n * 272 + k;
    } else {                               // v: K=272
        int j = i - 67584;
        int n = j / 272, k = j % 272;
        int kk = (k < 144) ? k : k + 128;
        w = Wv[kk * 128 + n];
        dh = g_Bv_h; dl = g_Bv_l; di = n * 272 + k;
    }
    __nv_bfloat16 h = __float2bfloat16(w);
    float r = w - __bfloat162float(h);
    dh[di] = h;
    dl[di] = __float2bfloat16(r);
}

// ---------------- HMMA GEMM (bf16x3, pipelined, 2 CTAs/SM) ------------------
#define BK 32
#define A_ST 40
#define B_ST 40
#define A_HALF (128 * A_ST * 2)
#define B_HALF (64 * B_ST * 2)
#define B_BASE (4 * A_HALF)
#define SMEM_TOTAL_TC (B_BASE + 6 * B_HALF)

__global__ __launch_bounds__(256, 2) void tc_gemm(
    int M,
    const float* __restrict__ Af, int KF,
    const float* __restrict__ Ah, const float* __restrict__ cnt,
    const float* __restrict__ Ae,
    const __nv_bfloat16* __restrict__ Bh, const __nv_bfloat16* __restrict__ Bl,
    int Ktot,
    const float* __restrict__ bias, const float* __restrict__ Q,
    const int* __restrict__ qidx, int act,
    float* __restrict__ out)
{
    extern __shared__ char smem[];
    const uint32_t sb = smem_u32(smem);
    const int tid  = threadIdx.x;
    const int wid  = tid >> 5;
    const int lane = tid & 31;

    const int row0 = blockIdx.x * 128;
    const int col0 = blockIdx.y * 64;

    const int r = tid >> 1;
    const int h = tid & 1;
    int grow = row0 + r;
    if (grow >= M) grow = M - 1;
    float inv = 1.f;
    if (cnt) inv = 1.f / fmaxf(cnt[grow], 1.f);

    const int brow = tid >> 2;
    const int bq   = (tid & 3) * 8;
    const __nv_bfloat16* bh_row = Bh + (size_t)(col0 + brow) * Ktot;
    const __nv_bfloat16* bl_row = Bl + (size_t)(col0 + brow) * Ktot;
    const uint32_t bdst = (uint32_t)(brow * B_ST + bq) * 2;

    const int nchunks = (Ktot + BK - 1) / BK;

    auto stage_b = [&](int c) {
        int s = c % 3;
        int gk = c * BK + bq;
        int rem = Ktot - gk;
        int sz = rem >= 8 ? 16 : 0;
        int gks = (rem >= 8) ? gk : (Ktot - 8);
        uint32_t dh = sb + B_BASE + (uint32_t)s * (2 * B_HALF) + bdst;
        CP_ASYNC16(dh, bh_row + gks, sz);
        CP_ASYNC16(dh + B_HALF, bl_row + gks, sz);
    };

    auto load_a = [&](int c, float4* va) {
        int k0 = c * BK;
#pragma unroll
        for (int j = 0; j < 4; j++) {
            int gk = k0 + h * 16 + j * 4;
            float4 v = make_float4(0.f, 0.f, 0.f, 0.f);
            if (gk < KF) {
                v = *(const float4*)(Af + (size_t)grow * KF + gk);
            } else if (gk < KF + 128) {
                v = *(const float4*)(Ah + (size_t)grow * 128 + (gk - KF));
                v.x *= inv; v.y *= inv; v.z *= inv; v.w *= inv;
            } else if (gk < Ktot) {
                v = *(const float4*)(Ae + (size_t)grow * 128 + (gk - KF - 128));
            }
            va[j] = v;
        }
    };

    const int m_base = (wid & 3) * 32;
    const int n_base = (wid >> 2) * 32;
    float acc[2][4][4];
#pragma unroll
    for (int mt = 0; mt < 2; mt++)
#pragma unroll
        for (int nt = 0; nt < 4; nt++)
            acc[mt][nt][0] = acc[mt][nt][1] = acc[mt][nt][2] = acc[mt][nt][3] = 0.f;

    const int lmA_row = lane & 15;
    const int lmA_ko  = (lane >> 4) * 8;
    const int lmB_n   = (lane & 7) + ((lane >> 4) & 1) * 8;
    const int lmB_ko  = ((lane >> 3) & 1) * 8;

    stage_b(0); CP_COMMIT();
    float4 va[4];
    load_a(0, va);

    for (int c = 0; c < nchunks; c++) {
        const int abuf = c & 1;
        const uint32_t a_hi = sb + (uint32_t)abuf * (2 * A_HALF);
        const uint32_t a_lo = a_hi + A_HALF;

#pragma unroll
        for (int j = 0; j < 4; j++) {
            int col = h * 16 + j * 4;
            uint2 hiv, lov;
            split2(va[j].x, va[j].y, hiv.x, lov.x);
            split2(va[j].z, va[j].w, hiv.y, lov.y);
            uint32_t off = (uint32_t)(r * A_ST + col) * 2;
            *(uint2*)(smem + (a_hi - sb) + off) = hiv;
            *(uint2*)(smem + (a_lo - sb) + off) = lov;
        }

        if (c + 1 < nchunks) {
            stage_b(c + 1); CP_COMMIT();
            load_a(c + 1, va);
            CP_WAIT(1);
        } else {
            CP_WAIT(0);
        }
        __syncthreads();

        const uint32_t b_hi = sb + B_BASE + (uint32_t)(c % 3) * (2 * B_HALF);
        const uint32_t b_lo = b_hi + B_HALF;

        const int ksteps = min(2, (Ktot - c * BK) >> 4);
#pragma unroll
        for (int ks = 0; ks < 2; ks++) {
            if (ks >= ksteps) break;
            uint32_t ah[2][4], al[2][4];
#pragma unroll
            for (int mt = 0; mt < 2; mt++) {
                uint32_t off =
                    (uint32_t)((m_base + mt * 16 + lmA_row) * A_ST +
                               ks * 16 + lmA_ko) * 2;
                LDM4(ah[mt], a_hi + off);
                LDM4(al[mt], a_lo + off);
            }
            uint32_t bhf[2][4], blf[2][4];
#pragma unroll
            for (int nt2 = 0; nt2 < 2; nt2++) {
                uint32_t off =
                    (uint32_t)((n_base + nt2 * 16 + lmB_n) * B_ST +
                               ks * 16 + lmB_ko) * 2;
                LDM4(bhf[nt2], b_hi + off);
                LDM4(blf[nt2], b_lo + off);
            }
#pragma unroll
            for (int mt = 0; mt < 2; mt++) {
#pragma unroll
                for (int nt = 0; nt < 4; nt++) {
                    uint32_t b0 = bhf[nt >> 1][(nt & 1) * 2];
                    uint32_t b1 = bhf[nt >> 1][(nt & 1) * 2 + 1];
                    uint32_t c0 = blf[nt >> 1][(nt & 1) * 2];
                    uint32_t c1 = blf[nt >> 1][(nt & 1) * 2 + 1];
                    MMA16816(acc[mt][nt], ah[mt], b0, b1);
                    MMA16816(acc[mt][nt], al[mt], b0, b1);
                    MMA16816(acc[mt][nt], ah[mt], c0, c1);
                }
            }
        }
    }

#pragma unroll
    for (int mt = 0; mt < 2; mt++) {
        int row_a = row0 + m_base + mt * 16 + (lane >> 2);
        int row_b = row_a + 8;
        const float* qa = nullptr;
        const float* qb = nullptr;
        if (Q) {
            if (row_a < M) qa = Q + (size_t)qidx[row_a] * 128;
            if (row_b < M) qb = Q + (size_t)qidx[row_b] * 128;
        }
#pragma unroll
        for (int nt = 0; nt < 4; nt++) {
            int col = col0 + n_base + nt * 8 + (lane & 3) * 2;
            float b0 = 0.f, b1 = 0.f;
            if (bias) { b0 = bias[col]; b1 = bias[col + 1]; }
            if (row_a < M) {
                float v0 = acc[mt][nt][0] + b0;
                float v1 = acc[mt][nt][1] + b1;
                if (qa) { v0 += qa[col]; v1 += qa[col + 1]; }
                if (act) { v0 = lrelu(v0); v1 = lrelu(v1); }
                *(float2*)(out + (size_t)row_a * 128 + col) = make_float2(v0, v1);
            }
            if (row_b < M) {
                float v0 = acc[mt][nt][2] + b0;
                float v1 = acc[mt][nt][3] + b1;
                if (qb) { v0 += qb[col]; v1 += qb[col + 1]; }
                if (act) { v0 = lrelu(v0); v1 = lrelu(v1); }
                *(float2*)(out + (size_t)row_b * 128 + col) = make_float2(v0, v1);
            }
        }
    }
}

// ---------------- small SIMT GEMM (tiny Q precomputes, M=64,K=128) ----------
__global__ __launch_bounds__(256, 2) void fused_gemm(
    int M,
    const float* __restrict__ Ah, const float* __restrict__ Wh,
    float* __restrict__ out)
{
    __shared__ float As[64][16];
    __shared__ float Ws[16][128];

    const int t  = threadIdx.x;
    const int tx = t & 31;
    const int ty = t >> 5;
    const int row0 = blockIdx.x * 64;

    float acc[8][4];
#pragma unroll
    for (int r = 0; r < 8; r++)
        acc[r][0] = acc[r][1] = acc[r][2] = acc[r][3] = 0.f;

    const int aRow = t >> 2;
    const int aK   = (t & 3) * 4;
    const int wK   = t >> 4;
    const int wC   = (t & 15) * 8;

    int arow_g = row0 + aRow;
    if (arow_g >= M) arow_g = M - 1;

    for (int kk = 0; kk < 128; kk += 16) {
        __syncthreads();
        float4 av = *(const float4*)(Ah + (size_t)arow_g * 128 + kk + aK);
        *(float4*)&As[aRow][aK] = av;
        const float* wp = Wh + (size_t)(kk + wK) * 128 + wC;
        *(float4*)&Ws[wK][wC]     = *(const float4*)(wp);
        *(float4*)&Ws[wK][wC + 4] = *(const float4*)(wp + 4);
        __syncthreads();

#pragma unroll
        for (int k = 0; k < 16; k++) {
            float4 w = *(const float4*)&Ws[k][tx * 4];
#pragma unroll
            for (int r = 0; r < 8; r++) {
                float a = As[ty * 8 + r][k];
                acc[r][0] = fmaf(a, w.x, acc[r][0]);
                acc[r][1] = fmaf(a, w.y, acc[r][1]);
                acc[r][2] = fmaf(a, w.z, acc[r][2]);
                acc[r][3] = fmaf(a, w.w, acc[r][3]);
            }
        }
    }

#pragma unroll
    for (int r = 0; r < 8; r++) {
        int row = row0 + ty * 8 + r;
        if (row < M) {
            float4 v = make_float4(acc[r][0], acc[r][1], acc[r][2], acc[r][3]);
            *(float4*)(out + (size_t)row * 128 + tx * 4) = v;
        }
    }
}

// ---------------- segment mean into NU=64 contexts --------------------------
__global__ __launch_bounds__(128) void seg_mean_ctx(
    const float* __restrict__ srcm, const int* __restrict__ ids, int n,
    float* __restrict__ acc, float* __restrict__ cntp)
{
    __shared__ float sacc[64 * 128];
    __shared__ float scnt[64];
    const int t = threadIdx.x;
    for (int i = t; i < 64 * 128; i += 128) sacc[i] = 0.f;
    if (t < 64) scnt[t] = 0.f;
    __syncthreads();

    for (long r0 = (long)blockIdx.x * 4; r0 < n; r0 += (long)gridDim.x * 4) {
        float v[4]; int id[4]; int k = 0;
#pragma unroll
        for (int u = 0; u < 4; u++) {
            long r = r0 + u;
            if (r < n) {
                id[k] = ids[r];
                v[k]  = srcm[(size_t)r * 128 + t];
                k++;
            }
        }
        for (int u = 0; u < k; u++) {
            sacc[id[u] * 128 + t] += v[u];
            if (t == 0) scnt[id[u]] += 1.f;
        }
    }
    __syncthreads();
    for (int i = t; i < 64 * 128; i += 128) atomicAdd(&acc[i], sacc[i]);
    if (t < 64) atomicAdd(&cntp[t], scnt[t]);
}

// ---------------- context update (64 rows, K=400) ---------------------------
__global__ __launch_bounds__(128) void ctx_update(
    const float* __restrict__ ctx_feats,
    const float* __restrict__ ctx_emb,
    const float* __restrict__ acc,
    const float* __restrict__ cntp,
    const float* __restrict__ Wu,
    const float* __restrict__ bu,
    float* __restrict__ out)
{
    const int u = blockIdx.x;
    const int t = threadIdx.x;
    __shared__ float a[400];

    if (t < 16) a[t] = ctx_feats[u * 16 + t];
    float cc = fmaxf(cntp[u], 1.f);
    float cv = fmaxf(cntp[64 + u], 1.f);
    a[16 + t]  = acc[u * 128 + t] / cc;
    a[144 + t] = acc[64 * 128 + u * 128 + t] / cv;
    a[272 + t] = ctx_emb[u * 128 + t];
    __syncthreads();

    float s = bu[t];
    for (int k = 0; k < 400; k++) s = fmaf(a[k], Wu[k * 128 + t], s);
    out[(size_t)u * 128 + t] = lrelu(s);
}

// ---------------- launch ----------------------------------------------------
extern "C" void kernel_launch(void* const* d_in, const int* in_sizes, int n_in,
                              void* d_out, int out_size)
{
    const float* var_emb      = (const float*)d_in[0];
    const float* clause_emb   = (const float*)d_in[1];
    const float* ctx_emb      = (const float*)d_in[2];
    const float* var_feats    = (const float*)d_in[3];
    const float* clause_feats = (const float*)d_in[4];
    const float* ctx_feats    = (const float*)d_in[5];
    const float* edge_sat_vc  = (const float*)d_in[6];
    const float* edge_sat_cv  = (const float*)d_in[7];
    const float* W_vc         = (const float*)d_in[8];
    const float* b_vc         = (const float*)d_in[9];
    const float* W_cv         = (const float*)d_in[10];
    const float* b_cv         = (const float*)d_in[11];
    const float* W_c          = (const float*)d_in[12];
    const float* b_c          = (const float*)d_in[13];
    const float* W_v          = (const float*)d_in[14];
    const float* b_v          = (const float*)d_in[15];
    const float* W_u          = (const float*)d_in[16];
    const float* b_u          = (const float*)d_in[17];
    const int* assigns_src    = (const int*)d_in[18];
    const int* assigns_dst    = (const int*)d_in[19];
    const int* contains_src   = (const int*)d_in[20];
    const int* contains_dst   = (const int*)d_in[21];
    const int* var_ctx        = (const int*)d_in[22];
    const int* clause_ctx     = (const int*)d_in[23];

    const int NV = in_sizes[0] / C_D;
    const int NC = in_sizes[1] / C_D;
    const int E  = in_sizes[18];
    const int NN = NC + NV;

    float *hc, *hv, *Pv, *Pc, *Qc, *Qv, *cacc, *ccnt;
    cudaGetSymbolAddress((void**)&hc,   g_hc);
    cudaGetSymbolAddress((void**)&hv,   g_hv);
    cudaGetSymbolAddress((void**)&Pv,   g_Pv);
    cudaGetSymbolAddress((void**)&Pc,   g_Pc);
    cudaGetSymbolAddress((void**)&Qc,   g_Qc);
    cudaGetSymbolAddress((void**)&Qv,   g_Qv);
    cudaGetSymbolAddress((void**)&cacc, g_ctx_acc);
    cudaGetSymbolAddress((void**)&ccnt, g_ctx_cnt);

    int *deg, *fill, *bsum, *ssrc1, *ssrc2;
    float *ses1, *ses2;
    cudaGetSymbolAddress((void**)&deg,   g_deg);
    cudaGetSymbolAddress((void**)&fill,  g_fill);
    cudaGetSymbolAddress((void**)&bsum,  g_bsum);
    cudaGetSymbolAddress((void**)&ssrc1, g_ssrc1);
    cudaGetSymbolAddress((void**)&ssrc2, g_ssrc2);
    cudaGetSymbolAddress((void**)&ses1,  g_ses1);
    cudaGetSymbolAddress((void**)&ses2,  g_ses2);

    __nv_bfloat16 *Bvc_h, *Bvc_l, *Bcv_h, *Bcv_l, *Bc_h, *Bc_l, *Bv_h, *Bv_l;
    cudaGetSymbolAddress((void**)&Bvc_h, g_Bvc_h);
    cudaGetSymbolAddress((void**)&Bvc_l, g_Bvc_l);
    cudaGetSymbolAddress((void**)&Bcv_h, g_Bcv_h);
    cudaGetSymbolAddress((void**)&Bcv_l, g_Bcv_l);
    cudaGetSymbolAddress((void**)&Bc_h,  g_Bc_h);
    cudaGetSymbolAddress((void**)&Bc_l,  g_Bc_l);
    cudaGetSymbolAddress((void**)&Bv_h,  g_Bv_h);
    cudaGetSymbolAddress((void**)&Bv_l,  g_Bv_l);

    float* out = (float*)d_out;

    cudaFuncSetAttribute(tc_gemm, cudaFuncAttributeMaxDynamicSharedMemorySize,
                         SMEM_TOTAL_TC);

    const int nb = (NN + 4095) / 4096;   // scan blocks

    // 0. zero small accumulators (deg, fill, ctx)
    zero_small<<<512, 256>>>(deg, fill, cacc, ccnt);
    // 1. weight transpose + split
    wprep<<<(102400 + 255) / 256, 256>>>(W_vc, W_cv, W_c, W_v);
    // 2. degree histogram (both directions)
    hist_kernel<<<(2 * E + 255) / 256, 256>>>(E, assigns_dst, contains_dst, deg);
    // 3-5. exclusive scan deg -> base (in g_deg? no: base stored over fill? )
    scanA<<<nb, 256>>>(deg, NN, deg /*in-place ok: scanA reads then writes*/, bsum);
    scanB<<<1, 32>>>(bsum, nb);
    scanC<<<(NN + 255) / 256, 256>>>(deg, bsum, NN);
    // (g_deg now holds exclusive-scan base; g_fill recovers degrees in scatter)
    // 6. scatter edges into destination order
    scatter_kernel<<<(2 * E + 255) / 256, 256>>>(
        E, assigns_src, assigns_dst, (const float4*)edge_sat_vc,
        contains_src, contains_dst, (const float4*)edge_sat_cv,
        deg, fill, ssrc1, (float4*)ses1, ssrc2, (float4*)ses2);

    // 7. P_v = var_emb @ W_vc[4:132]   (HMMA)
    tc_gemm<<<dim3((NV + 127) / 128, 2), 256, SMEM_TOTAL_TC>>>(
        NV, nullptr, 0, var_emb, nullptr, nullptr,
        Bvc_h, Bvc_l, 128, nullptr, nullptr, nullptr, 0, Pv);
    // 8. P_c = clause_emb @ W_cv[4:132] (HMMA)
    tc_gemm<<<dim3((NC + 127) / 128, 2), 256, SMEM_TOTAL_TC>>>(
        NC, nullptr, 0, clause_emb, nullptr, nullptr,
        Bcv_h, Bcv_l, 128, nullptr, nullptr, nullptr, 0, Pc);

    // 9. Q_c = ctx_emb @ W_c[144:272]  (tiny, SIMT)
    fused_gemm<<<1, 256>>>(C_NU, ctx_emb, W_c + 144 * C_D, Qc);

    // 10. aggregate dir1: var -> clause (writes hc, pre-divided by deg)
    agg_kernel<<<(NC + 7) / 8, 256>>>(
        NC, 0, 0, deg, fill, ssrc1, (const float4*)ses1, Pv, W_vc, b_vc, hc);
    // 11. aggregate dir2: clause -> var (writes hv)
    agg_kernel<<<(NV + 7) / 8, 256>>>(
        NV, NC, E, deg, fill, ssrc2, (const float4*)ses2, Pc, W_cv, b_cv, hv);

    // 12. Q_v = ctx_emb @ W_v[144:272]
    fused_gemm<<<1, 256>>>(C_NU, ctx_emb, W_v + 144 * C_D, Qv);

    // 13. new_clause (HMMA, fused epilogue) -> out rows [0, NC)
    tc_gemm<<<dim3((NC + 127) / 128, 2), 256, SMEM_TOTAL_TC>>>(
        NC, clause_feats, 16, hc, nullptr, clause_emb,
        Bc_h, Bc_l, 272, b_c, Qc, clause_ctx, 1, out);
    // 14. new_var (HMMA) -> out rows [NC, NC+NV)
    tc_gemm<<<dim3((NV + 127) / 128, 2), 256, SMEM_TOTAL_TC>>>(
        NV, var_feats, 16, hv, nullptr, var_emb,
        Bv_h, Bv_l, 272, b_v, Qv, var_ctx, 1, out + (size_t)NC * C_D);

    // 15-16. context means over the NEW embeddings
    seg_mean_ctx<<<1024, 128>>>(out, clause_ctx, NC, cacc, ccnt);
    seg_mean_ctx<<<1024, 128>>>(out + (size_t)NC * C_D, var_ctx, NV,
                                cacc + C_NU * C_D, ccnt + C_NU);

    // 17. context update: rows [NC+NV, NC+NV+NU)
    ctx_update<<<C_NU, 128>>>(ctx_feats, ctx_emb, cacc, ccnt, W_u, b_u,
                              out + (size_t)(NC + NV) * C_D);
}